// round 10
// baseline (speedup 1.0000x reference)
#include <cuda_runtime.h>
#include <cstdint>

#define SEQ 400
#define BATCH 8
#define DM 256          // d_model
#define SD 512          // source_dim
#define PW 768          // packed projection width: [Q | K | Q2W]
#define ND2 896         // delta columns padded (799 real)
#define BS (BATCH*SEQ)          // 3200
#define BSS (BATCH*SEQ*SEQ)     // 1280000

// Scratch (device globals — no allocations allowed)
__device__ float g_Xt[BS*SD];        // tf32-rounded x              (3200x512)
__device__ float g_Wcat[SD*PW];      // [w_q | w_k | w_q2@w_k2^T]   (512x768) tf32
__device__ float g_P[BS*PW];         // Xt @ Wcat                   (3200x768) tf32
__device__ float g_RT[DM*ND2];       // R^T: [d][delta+399]         (256x896) tf32
__device__ float g_S[BS*ND2];        // P[:,512:768] @ RT           (3200x896) fp32

// ---------------------------------------------------------------------------
__device__ __forceinline__ float f2tf32(float f) {
    uint32_t u;
    asm("cvt.rna.tf32.f32 %0, %1;" : "=r"(u) : "f"(f));
    return __uint_as_float(u);
}

__device__ __forceinline__ void mma8(float c[4], const uint32_t a[4], const uint32_t b[2]) {
    asm volatile("mma.sync.aligned.m16n8k8.row.col.f32.tf32.tf32.f32 "
        "{%0,%1,%2,%3}, {%4,%5,%6,%7}, {%8,%9}, {%0,%1,%2,%3};"
        : "+f"(c[0]), "+f"(c[1]), "+f"(c[2]), "+f"(c[3])
        : "r"(a[0]), "r"(a[1]), "r"(a[2]), "r"(a[3]), "r"(b[0]), "r"(b[1]));
}

__device__ __forceinline__ void cpa16(uint32_t dst, const float* src, bool p) {
    asm volatile("cp.async.cg.shared.global [%0], [%1], 16, %2;"
                 :: "r"(dst), "l"(src), "r"(p ? 16 : 0));
}
__device__ __forceinline__ void cpa_commit() {
    asm volatile("cp.async.commit_group;");
}
template <int N>
__device__ __forceinline__ void cpa_wait() {
    asm volatile("cp.async.wait_group %0;" :: "n"(N));
}

// ---------------------------------------------------------------------------
// Fused setup kernel — all sections independent, one launch, 256 threads:
//   S0: Xt = tf32(x)                                  blocks [0, 1600)
//   S1: Wcat[:, 0:512) = tf32([w_q | w_k])            blocks [1600, 1728)
//   S2: RT (smem-transposed gather, tf32)             blocks [1728, 1840)
//   S3: Wcat[:, 512:768) = tf32(w_q2 @ w_k2^T)        blocks [1840, 1872)
//   S4: out[BSS..2BSS) = mask outer product           blocks [1872, 3122)
// ---------------------------------------------------------------------------
#define SB0 1600
#define SB1 (SB0 + 128)
#define SB2 (SB1 + 112)
#define SB3 (SB2 + 32)
#define SB4 (SB3 + 1250)

__global__ __launch_bounds__(256)
void setup_all(const float* __restrict__ x,
               const float* __restrict__ wq, const float* __restrict__ wk,
               const float* __restrict__ wq2, const float* __restrict__ wk2,
               const float* __restrict__ rel, const int* __restrict__ mask,
               float* __restrict__ Xt, float* __restrict__ Wcat,
               float* __restrict__ RT, float* __restrict__ out, int out_size)
{
    __shared__ float sh[2176 * 2];   // 17408 B: fits S2 (32x65) and S3 (2x16x68)
    const int blk = blockIdx.x;
    const int tid = threadIdx.x;

    if (blk < SB0) {
        // ---- S0: tf32-round x
        const int idx = blk * 256 + tid;
        float4 v = ((const float4*)x)[idx];
        v.x = f2tf32(v.x); v.y = f2tf32(v.y); v.z = f2tf32(v.z); v.w = f2tf32(v.w);
        ((float4*)Xt)[idx] = v;
    } else if (blk < SB1) {
        // ---- S1: pack w_q, w_k
        const int idx = (blk - SB0) * 256 + tid;
        const int row = idx / (DM / 4);
        const int c4  = idx % (DM / 4);
        float4 q = ((const float4*)wq)[idx];
        float4 k = ((const float4*)wk)[idx];
        q.x = f2tf32(q.x); q.y = f2tf32(q.y); q.z = f2tf32(q.z); q.w = f2tf32(q.w);
        k.x = f2tf32(k.x); k.y = f2tf32(k.y); k.z = f2tf32(k.z); k.w = f2tf32(k.w);
        ((float4*)(Wcat + (long)row * PW))[c4] = q;
        ((float4*)(Wcat + (long)row * PW + DM))[c4] = k;
    } else if (blk < SB2) {
        // ---- S2: RT transposed gather. Tile: 32 m x 64 d, smem transpose.
        float (*t)[65] = (float(*)[65])sh;
        const int blk2 = blk - SB1;
        const int m0 = (blk2 % 28) * 32;
        const int d0 = (blk2 / 28) * 64;
        const int dl = tid & 63, mb = tid >> 6;      // load: 64 d-lanes x 4 m
#pragma unroll
        for (int it = 0; it < 8; it++) {
            const int ml = mb * 8 + it;
            const int m = m0 + ml;
            float v = 0.f;
            if (m <= 798) {
                const int delta = m - 399;
                const long off = (delta >= 0) ? (long)delta * DM
                                              : (long)(-delta) * SEQ * DM;
                v = f2tf32(rel[off + d0 + dl]);
            }
            t[ml][dl] = v;
        }
        __syncthreads();
        const int ml2 = tid & 31, db = tid >> 5;     // store: 32 m-lanes x 8 d
#pragma unroll
        for (int it = 0; it < 8; it++) {
            const int dl2 = db + it * 8;
            RT[(long)(d0 + dl2) * ND2 + m0 + ml2] = t[ml2][dl2];
        }
    } else if (blk < SB3) {
        // ---- S3: W2 = w_q2 @ w_k2^T -> Wcat cols [512:768), fp32 SIMT
        float (*As)[68] = (float(*)[68])sh;
        float (*Bs)[68] = (float(*)[68])(sh + 16 * 68);
        const int blk2 = blk - SB2;
        const int m0 = (blk2 >> 2) * 64, n0 = (blk2 & 3) * 64;
        const int tx = tid & 15, ty = tid >> 4;
        const int ar = tid >> 2, ak = (tid & 3) * 4;
        float acc[4][4] = {};
        for (int k0 = 0; k0 < DM; k0 += 16) {
            float4 v = *(const float4*)(wq2 + (long)(m0 + ar) * DM + k0 + ak);
            As[ak][ar] = v.x; As[ak+1][ar] = v.y; As[ak+2][ar] = v.z; As[ak+3][ar] = v.w;
            float4 w = *(const float4*)(wk2 + (long)(n0 + ar) * DM + k0 + ak);
            Bs[ak][ar] = w.x; Bs[ak+1][ar] = w.y; Bs[ak+2][ar] = w.z; Bs[ak+3][ar] = w.w;
            __syncthreads();
#pragma unroll
            for (int kk = 0; kk < 16; kk++) {
                const float4 a = *(const float4*)&As[kk][ty * 4];
                const float4 b = *(const float4*)&Bs[kk][tx * 4];
                acc[0][0]+=a.x*b.x; acc[0][1]+=a.x*b.y; acc[0][2]+=a.x*b.z; acc[0][3]+=a.x*b.w;
                acc[1][0]+=a.y*b.x; acc[1][1]+=a.y*b.y; acc[1][2]+=a.y*b.z; acc[1][3]+=a.y*b.w;
                acc[2][0]+=a.z*b.x; acc[2][1]+=a.z*b.y; acc[2][2]+=a.z*b.z; acc[2][3]+=a.z*b.w;
                acc[3][0]+=a.w*b.x; acc[3][1]+=a.w*b.y; acc[3][2]+=a.w*b.z; acc[3][3]+=a.w*b.w;
            }
            __syncthreads();
        }
#pragma unroll
        for (int r = 0; r < 4; r++)
#pragma unroll
            for (int c = 0; c < 4; c++)
                Wcat[(long)(m0 + ty*4 + r) * PW + SD + n0 + tx*4 + c] = f2tf32(acc[r][c]);
    } else if (blk < SB4) {
        // ---- S4: mask outer product into out[BSS..2BSS)
        if (out_size < 2 * BSS) return;
        const int i4 = (blk - SB3) * 256 + tid;
        const long idx = (long)i4 * 4;
        if (idx >= BSS) return;
        const int j = (int)(idx % SEQ);
        const int bi = (int)(idx / SEQ);
        const int i = bi % SEQ, b = bi / SEQ;
        const float mi = (float)mask[b * SEQ + i];
        float4 o;
        o.x = mi * mask[b * SEQ + j];
        o.y = mi * mask[b * SEQ + j + 1];
        o.z = mi * mask[b * SEQ + j + 2];
        o.w = mi * mask[b * SEQ + j + 3];
        *(float4*)&out[BSS + idx] = o;
    }
}

// ---------------------------------------------------------------------------
// tf32 tensor-core GEMM v5. 128x128 block, BK=16, 256 threads (8 warps,
// 64x32 warp tiles, 4x4 m16n8k8). THREE-stage cp.async pipeline
// (wait_group 1: two groups in flight) in dynamic smem; padded layouts
// conflict-free (A/B-NT rows pad 20; B-NN rows pad 136).
//
// NTB=false: C = A[M,K] @ B[K,N]; requires M%128==0, N%128==0.
// NTB=true : C = A[M,K] @ B[N,K]^T; M,N bounded by Mreal/Nreal (zfill).
// ECOMB: fused epilogue out = (acc + gather(S))/16 (mask handled in setup).
// OTF: tf32-round C on store.
// ---------------------------------------------------------------------------
template <bool NTB, bool ECOMB, bool OTF>
__global__ __launch_bounds__(256)
void mmaT(const float* __restrict__ A, const float* __restrict__ B,
          float* __restrict__ C,
          int Mreal, int Nreal, int K, int lda, int ldb, int ldc,
          long sA, long sB,
          const float* __restrict__ S, float* __restrict__ out, int out_size)
{
    constexpr int BR  = NTB ? 128 : 16;
    constexpr int BC  = NTB ? 20 : 136;
    constexpr int ASZ = 128 * 20;
    constexpr int BSZ = BR * BC;
    extern __shared__ float sh[];
    float* Asb = sh;                 // 3 stages of A
    float* Bsb = sh + 3 * ASZ;       // 3 stages of B

    const int tid  = threadIdx.x;
    const int lane = tid & 31;
    const int wid  = tid >> 5;      // 0..7
    const int wm   = wid >> 2;      // 0..1
    const int wn   = wid & 3;       // 0..3
    const int m0   = blockIdx.y * 128;
    const int n0   = blockIdx.x * 128;

    A += blockIdx.z * sA;
    B += blockIdx.z * sB;

    const uint32_t uA = (uint32_t)__cvta_generic_to_shared(Asb);
    const uint32_t uB = (uint32_t)__cvta_generic_to_shared(Bsb);

    // ---- A loader: quads tid and tid+256; row=q>>2, kq=(q&3)*4.
    const int ar1 = tid >> 2;            // 0..63
    const int ar2 = ar1 + 64;            // 64..127
    const int akq = (tid & 3) * 4;       // 0,4,8,12
    const bool aok1 = (m0 + ar1) < Mreal;
    const bool aok2 = (m0 + ar2) < Mreal;
    const float* aptr1 = A + (long)(aok1 ? (m0 + ar1) : 0) * lda + akq;
    const float* aptr2 = A + (long)(aok2 ? (m0 + ar2) : 0) * lda + akq;
    const uint32_t adst1 = uA + (uint32_t)(ar1 * 20 + akq) * 4;
    const uint32_t adst2 = uA + (uint32_t)(ar2 * 20 + akq) * 4;

    // ---- B loader
    const float *bptr1, *bptr2;
    uint32_t bdst1, bdst2;
    bool bok1 = true, bok2 = true;
    if (NTB) {
        const int br1 = tid >> 2, br2 = br1 + 64;
        bok1 = (n0 + br1) < Nreal;
        bok2 = (n0 + br2) < Nreal;
        bptr1 = B + (long)(bok1 ? (n0 + br1) : 0) * ldb + akq;
        bptr2 = B + (long)(bok2 ? (n0 + br2) : 0) * ldb + akq;
        bdst1 = uB + (uint32_t)(br1 * 20 + akq) * 4;
        bdst2 = uB + (uint32_t)(br2 * 20 + akq) * 4;
    } else {
        const int brow = tid >> 5;          // 0..7 (second: +8)
        const int bcol = (tid & 31) * 4;    // 0..124
        bptr1 = B + (long)brow * ldb + n0 + bcol;
        bptr2 = B + (long)(brow + 8) * ldb + n0 + bcol;
        bdst1 = uB + (uint32_t)(brow * BC + bcol) * 4;
        bdst2 = uB + (uint32_t)((brow + 8) * BC + bcol) * 4;
    }

    float acc[4][4][4];
#pragma unroll
    for (int mt = 0; mt < 4; mt++)
#pragma unroll
        for (int nt = 0; nt < 4; nt++)
#pragma unroll
            for (int r = 0; r < 4; r++) acc[mt][nt][r] = 0.f;

    auto load_stage = [&](int buf, int k0) {
        const uint32_t ao = (uint32_t)buf * (ASZ * 4);
        const uint32_t bo = (uint32_t)buf * (BSZ * 4);
        cpa16(adst1 + ao, aptr1 + k0, aok1);
        cpa16(adst2 + ao, aptr2 + k0, aok2);
        if (NTB) {
            cpa16(bdst1 + bo, bptr1 + k0, bok1);
            cpa16(bdst2 + bo, bptr2 + k0, bok2);
        } else {
            cpa16(bdst1 + bo, bptr1 + (long)k0 * ldb, true);
            cpa16(bdst2 + bo, bptr2 + (long)k0 * ldb, true);
        }
        cpa_commit();
    };

    const int nk = K >> 4;              // >= 2 at all call sites
    load_stage(0, 0);
    load_stage(1, 16);

    int buf = 0;
    for (int kt = 0; kt < nk; kt++) {
        // stage kt resident once <=1 newer group pending (max 2 in flight)
        if (kt + 1 < nk) cpa_wait<1>(); else cpa_wait<0>();
        __syncthreads();

        // refill the buffer consumed at kt-1 (all threads passed the barrier)
        if (kt + 2 < nk) {
            int nb = buf + 2; if (nb >= 3) nb -= 3;
            load_stage(nb, (kt + 2) << 4);
        }

        const float* Astage = Asb + buf * ASZ;
        const float* Bstage = Bsb + buf * BSZ;
#pragma unroll
        for (int h = 0; h < 2; h++) {
            const int c = h * 8 + (lane & 3);
            uint32_t af[4][4];
            uint32_t bf[4][2];
            const float* abase = Astage + (wm * 64 + (lane >> 2)) * 20 + c;
#pragma unroll
            for (int mt = 0; mt < 4; mt++) {
                af[mt][0] = __float_as_uint(abase[(mt * 16    ) * 20    ]);
                af[mt][1] = __float_as_uint(abase[(mt * 16 + 8) * 20    ]);
                af[mt][2] = __float_as_uint(abase[(mt * 16    ) * 20 + 4]);
                af[mt][3] = __float_as_uint(abase[(mt * 16 + 8) * 20 + 4]);
            }
#pragma unroll
            for (int nt = 0; nt < 4; nt++) {
                const int nB = wn * 32 + nt * 8 + (lane >> 2);
                if (NTB) {
                    bf[nt][0] = __float_as_uint(Bstage[nB * BC + c]);
                    bf[nt][1] = __float_as_uint(Bstage[nB * BC + c + 4]);
                } else {
                    bf[nt][0] = __float_as_uint(Bstage[c * BC + nB]);
                    bf[nt][1] = __float_as_uint(Bstage[(c + 4) * BC + nB]);
                }
            }
#pragma unroll
            for (int mt = 0; mt < 4; mt++)
#pragma unroll
                for (int nt = 0; nt < 4; nt++)
                    mma8(acc[mt][nt], af[mt], bf[nt]);
        }

        buf++; if (buf == 3) buf = 0;
        if (kt + 1 < nk) __syncthreads();   // protect buffer reuse ordering
    }

    // ---- epilogue ----
    if (!ECOMB) {
#pragma unroll
        for (int mt = 0; mt < 4; mt++) {
            const int r0 = m0 + wm * 64 + mt * 16 + (lane >> 2);
            const int r1 = r0 + 8;
#pragma unroll
            for (int nt = 0; nt < 4; nt++) {
                const int cc = n0 + wn * 32 + nt * 8 + (lane & 3) * 2;
                float v0 = acc[mt][nt][0], v1 = acc[mt][nt][1];
                float v2 = acc[mt][nt][2], v3 = acc[mt][nt][3];
                if (OTF) { v0 = f2tf32(v0); v1 = f2tf32(v1); v2 = f2tf32(v2); v3 = f2tf32(v3); }
                *(float2*)&C[(long)r0 * ldc + cc] = make_float2(v0, v1);
                *(float2*)&C[(long)r1 * ldc + cc] = make_float2(v2, v3);
            }
        }
    } else {
        const int b = blockIdx.z;
#pragma unroll
        for (int mt = 0; mt < 4; mt++) {
            const int ibase = m0 + wm * 64 + mt * 16 + (lane >> 2);
#pragma unroll
            for (int half = 0; half < 2; half++) {
                const int i = ibase + half * 8;
                if (i >= SEQ) continue;
                const float* srow = S + (long)(b * SEQ + i) * ND2 + (399 - i);
                const long obase = (long)b * SEQ * SEQ + (long)i * SEQ;
#pragma unroll
                for (int nt = 0; nt < 4; nt++) {
                    const int cc = n0 + wn * 32 + nt * 8 + (lane & 3) * 2;
                    if (cc >= SEQ) continue;   // cc even, so cc+1 <= 399
                    const float v0 = (acc[mt][nt][half * 2 + 0] + srow[cc])     * 0.0625f;
                    const float v1 = (acc[mt][nt][half * 2 + 1] + srow[cc + 1]) * 0.0625f;
                    *(float2*)&out[obase + cc] = make_float2(v0, v1);
                }
            }
        }
    }
}

extern "C" void kernel_launch(void* const* d_in, const int* in_sizes, int n_in,
                              void* d_out, int out_size)
{
    const float* x    = (const float*)d_in[0];  // (8,400,512)
    const int*   mask = (const int*)  d_in[1];  // (8,400)
    const float* w_q  = (const float*)d_in[2];  // (512,256)
    const float* w_q2 = (const float*)d_in[3];  // (512,256)
    const float* w_k  = (const float*)d_in[4];  // (512,256)
    const float* w_k2 = (const float*)d_in[5];  // (256,256)
    const float* rel  = (const float*)d_in[6];  // (1,400,400,256)
    float* out = (float*)d_out;

    float *Xt, *Wcat, *P, *RT, *S;
    cudaGetSymbolAddress((void**)&Xt,   g_Xt);
    cudaGetSymbolAddress((void**)&Wcat, g_Wcat);
    cudaGetSymbolAddress((void**)&P,    g_P);
    cudaGetSymbolAddress((void**)&RT,   g_RT);
    cudaGetSymbolAddress((void**)&S,    g_S);

    // Dynamic smem sizes: 3 stages of (A + B) tiles
    const int smemNN = 3 * (128 * 20 + 16 * 136) * 4;    // 56832 B
    const int smemNT = 3 * (128 * 20 + 128 * 20) * 4;    // 61440 B
    cudaFuncSetAttribute(mmaT<false, false, true>,
        cudaFuncAttributeMaxDynamicSharedMemorySize, smemNN);
    cudaFuncSetAttribute(mmaT<false, false, false>,
        cudaFuncAttributeMaxDynamicSharedMemorySize, smemNN);
    cudaFuncSetAttribute(mmaT<true, true, false>,
        cudaFuncAttributeMaxDynamicSharedMemorySize, smemNT);

    // 1) All setup in one launch (Xt, Wcat, RT, mask half of out)
    setup_all<<<SB4, 256>>>(x, w_q, w_k, w_q2, w_k2, rel, mask,
                            Xt, Wcat, RT, out, out_size);

    // 2) P = Xt @ Wcat  (3200x768x512), output tf32-rounded
    mmaT<false, false, true><<<dim3(PW / 128, BS / 128), 256, smemNN>>>(
        Xt, Wcat, P, BS, PW, SD, SD, PW, PW, 0, 0, nullptr, nullptr, 0);

    // 3) S = P[:,512:768) @ RT  (3200x896x256), output fp32
    mmaT<false, false, false><<<dim3(ND2 / 128, BS / 128), 256, smemNN>>>(
        P + SD, RT, S, BS, ND2, DM, PW, ND2, ND2, 0, 0, nullptr, nullptr, 0);

    // 4) E = Q @ K^T fused with combine, batched over z
    mmaT<true, true, false><<<dim3(4, 4, BATCH), 256, smemNT>>>(
        P, P + DM, nullptr, SEQ, SEQ, DM, PW, PW, 0,
        (long)SEQ * PW, (long)SEQ * PW, S, out, out_size);
}

// round 11
// speedup vs baseline: 1.5100x; 1.5100x over previous
#include <cuda_runtime.h>
#include <cstdint>

#define SEQ 400
#define BATCH 8
#define DM 256          // d_model
#define SD 512          // source_dim
#define PW 768          // packed projection width: [Q | K | Q2W]
#define ND2 896         // delta columns padded (799 real)
#define BS (BATCH*SEQ)          // 3200
#define BSS (BATCH*SEQ*SEQ)     // 1280000

// Scratch (device globals — no allocations allowed)
__device__ float g_Xt[BS*SD];        // tf32-rounded x              (3200x512)
__device__ float g_Wcat[SD*PW];      // [w_q | w_k | w_q2@w_k2^T]   (512x768) tf32
__device__ float g_P[BS*PW];         // Xt @ Wcat                   (3200x768) tf32
__device__ float g_RT[DM*ND2];       // R^T: [d][delta+399]         (256x896) tf32
__device__ float g_S[BS*ND2];        // P[:,512:768] @ RT           (3200x896) fp32

// ---------------------------------------------------------------------------
__device__ __forceinline__ float f2tf32(float f) {
    uint32_t u;
    asm("cvt.rna.tf32.f32 %0, %1;" : "=r"(u) : "f"(f));
    return __uint_as_float(u);
}

__device__ __forceinline__ void mma8(float c[4], const uint32_t a[4], const uint32_t b[2]) {
    asm volatile("mma.sync.aligned.m16n8k8.row.col.f32.tf32.tf32.f32 "
        "{%0,%1,%2,%3}, {%4,%5,%6,%7}, {%8,%9}, {%0,%1,%2,%3};"
        : "+f"(c[0]), "+f"(c[1]), "+f"(c[2]), "+f"(c[3])
        : "r"(a[0]), "r"(a[1]), "r"(a[2]), "r"(a[3]), "r"(b[0]), "r"(b[1]));
}

__device__ __forceinline__ void cpa16(uint32_t dst, const float* src, bool p) {
    asm volatile("cp.async.cg.shared.global [%0], [%1], 16, %2;"
                 :: "r"(dst), "l"(src), "r"(p ? 16 : 0));
}
__device__ __forceinline__ void cpa_commit() {
    asm volatile("cp.async.commit_group;");
}
__device__ __forceinline__ void cpa_wait0() {
    asm volatile("cp.async.wait_group 0;");
}

// ---------------------------------------------------------------------------
// Fused setup kernel — all sections independent, one launch, 256 threads:
//   S0: Xt = tf32(x)                                  blocks [0, 1600)
//   S1: Wcat[:, 0:512) = tf32([w_q | w_k])            blocks [1600, 1728)
//   S2: RT (smem-transposed gather, tf32)             blocks [1728, 1840)
//   S3: Wcat[:, 512:768) = tf32(w_q2 @ w_k2^T)        blocks [1840, 1872)
//   S4: out[BSS..2BSS) = mask outer product           blocks [1872, 3122)
// ---------------------------------------------------------------------------
#define SB0 1600
#define SB1 (SB0 + 128)
#define SB2 (SB1 + 112)
#define SB3 (SB2 + 32)
#define SB4 (SB3 + 1250)

__global__ __launch_bounds__(256)
void setup_all(const float* __restrict__ x,
               const float* __restrict__ wq, const float* __restrict__ wk,
               const float* __restrict__ wq2, const float* __restrict__ wk2,
               const float* __restrict__ rel, const int* __restrict__ mask,
               float* __restrict__ Xt, float* __restrict__ Wcat,
               float* __restrict__ RT, float* __restrict__ out, int out_size)
{
    __shared__ float sh[2176 * 2];   // 17408 B: fits S2 (32x65) and S3 (2x16x68)
    const int blk = blockIdx.x;
    const int tid = threadIdx.x;

    if (blk < SB0) {
        // ---- S0: tf32-round x
        const int idx = blk * 256 + tid;
        float4 v = ((const float4*)x)[idx];
        v.x = f2tf32(v.x); v.y = f2tf32(v.y); v.z = f2tf32(v.z); v.w = f2tf32(v.w);
        ((float4*)Xt)[idx] = v;
    } else if (blk < SB1) {
        // ---- S1: pack w_q, w_k
        const int idx = (blk - SB0) * 256 + tid;
        const int row = idx / (DM / 4);
        const int c4  = idx % (DM / 4);
        float4 q = ((const float4*)wq)[idx];
        float4 k = ((const float4*)wk)[idx];
        q.x = f2tf32(q.x); q.y = f2tf32(q.y); q.z = f2tf32(q.z); q.w = f2tf32(q.w);
        k.x = f2tf32(k.x); k.y = f2tf32(k.y); k.z = f2tf32(k.z); k.w = f2tf32(k.w);
        ((float4*)(Wcat + (long)row * PW))[c4] = q;
        ((float4*)(Wcat + (long)row * PW + DM))[c4] = k;
    } else if (blk < SB2) {
        // ---- S2: RT transposed gather. Tile: 32 m x 64 d, smem transpose.
        float (*t)[65] = (float(*)[65])sh;
        const int blk2 = blk - SB1;
        const int m0 = (blk2 % 28) * 32;
        const int d0 = (blk2 / 28) * 64;
        const int dl = tid & 63, mb = tid >> 6;      // load: 64 d-lanes x 4 m
#pragma unroll
        for (int it = 0; it < 8; it++) {
            const int ml = mb * 8 + it;
            const int m = m0 + ml;
            float v = 0.f;
            if (m <= 798) {
                const int delta = m - 399;
                const long off = (delta >= 0) ? (long)delta * DM
                                              : (long)(-delta) * SEQ * DM;
                v = f2tf32(rel[off + d0 + dl]);
            }
            t[ml][dl] = v;
        }
        __syncthreads();
        const int ml2 = tid & 31, db = tid >> 5;     // store: 32 m-lanes x 8 d
#pragma unroll
        for (int it = 0; it < 8; it++) {
            const int dl2 = db + it * 8;
            RT[(long)(d0 + dl2) * ND2 + m0 + ml2] = t[ml2][dl2];
        }
    } else if (blk < SB3) {
        // ---- S3: W2 = w_q2 @ w_k2^T -> Wcat cols [512:768), fp32 SIMT
        float (*As)[68] = (float(*)[68])sh;
        float (*Bs)[68] = (float(*)[68])(sh + 16 * 68);
        const int blk2 = blk - SB2;
        const int m0 = (blk2 >> 2) * 64, n0 = (blk2 & 3) * 64;
        const int tx = tid & 15, ty = tid >> 4;
        const int ar = tid >> 2, ak = (tid & 3) * 4;
        float acc[4][4] = {};
        for (int k0 = 0; k0 < DM; k0 += 16) {
            float4 v = *(const float4*)(wq2 + (long)(m0 + ar) * DM + k0 + ak);
            As[ak][ar] = v.x; As[ak+1][ar] = v.y; As[ak+2][ar] = v.z; As[ak+3][ar] = v.w;
            float4 w = *(const float4*)(wk2 + (long)(n0 + ar) * DM + k0 + ak);
            Bs[ak][ar] = w.x; Bs[ak+1][ar] = w.y; Bs[ak+2][ar] = w.z; Bs[ak+3][ar] = w.w;
            __syncthreads();
#pragma unroll
            for (int kk = 0; kk < 16; kk++) {
                const float4 a = *(const float4*)&As[kk][ty * 4];
                const float4 b = *(const float4*)&Bs[kk][tx * 4];
                acc[0][0]+=a.x*b.x; acc[0][1]+=a.x*b.y; acc[0][2]+=a.x*b.z; acc[0][3]+=a.x*b.w;
                acc[1][0]+=a.y*b.x; acc[1][1]+=a.y*b.y; acc[1][2]+=a.y*b.z; acc[1][3]+=a.y*b.w;
                acc[2][0]+=a.z*b.x; acc[2][1]+=a.z*b.y; acc[2][2]+=a.z*b.z; acc[2][3]+=a.z*b.w;
                acc[3][0]+=a.w*b.x; acc[3][1]+=a.w*b.y; acc[3][2]+=a.w*b.z; acc[3][3]+=a.w*b.w;
            }
            __syncthreads();
        }
#pragma unroll
        for (int r = 0; r < 4; r++)
#pragma unroll
            for (int c = 0; c < 4; c++)
                Wcat[(long)(m0 + ty*4 + r) * PW + SD + n0 + tx*4 + c] = f2tf32(acc[r][c]);
    } else if (blk < SB4) {
        // ---- S4: mask outer product into out[BSS..2BSS)
        if (out_size < 2 * BSS) return;
        const int i4 = (blk - SB3) * 256 + tid;
        const long idx = (long)i4 * 4;
        if (idx >= BSS) return;
        const int j = (int)(idx % SEQ);
        const int bi = (int)(idx / SEQ);
        const int i = bi % SEQ, b = bi / SEQ;
        const float mi = (float)mask[b * SEQ + i];
        float4 o;
        o.x = mi * mask[b * SEQ + j];
        o.y = mi * mask[b * SEQ + j + 1];
        o.z = mi * mask[b * SEQ + j + 2];
        o.w = mi * mask[b * SEQ + j + 3];
        *(float4*)&out[BSS + idx] = o;
    }
}

// ---------------------------------------------------------------------------
// tf32 tensor-core GEMM (R9 proven version). 128x128 block, BK=16, 256
// threads (8 warps, 64x32 warp tiles, 4x4 m16n8k8). Two-stage cp.async,
// static smem, one barrier per k-tile. NN only (used for P and S GEMMs).
// Requires M%128==0, N%128==0, K%16==0. OTF: tf32-round C on store.
// ---------------------------------------------------------------------------
template <bool OTF>
__global__ __launch_bounds__(256)
void mmaT(const float* __restrict__ A, const float* __restrict__ B,
          float* __restrict__ C, int K, int lda, int ldb, int ldc)
{
    constexpr int BC = 136;
    __shared__ float As[2][128][20];
    __shared__ float Bs[2][16][BC];

    const int tid  = threadIdx.x;
    const int lane = tid & 31;
    const int wid  = tid >> 5;      // 0..7
    const int wm   = wid >> 2;      // 0..1
    const int wn   = wid & 3;       // 0..3
    const int m0   = blockIdx.y * 128;
    const int n0   = blockIdx.x * 128;

    const uint32_t uA = (uint32_t)__cvta_generic_to_shared(&As[0][0][0]);
    const uint32_t uB = (uint32_t)__cvta_generic_to_shared(&Bs[0][0][0]);

    // ---- A loader: quads tid and tid+256; row=q>>2, kq=(q&3)*4.
    const int ar1 = tid >> 2;            // 0..63
    const int ar2 = ar1 + 64;            // 64..127
    const int akq = (tid & 3) * 4;       // 0,4,8,12
    const float* aptr1 = A + (long)(m0 + ar1) * lda + akq;
    const float* aptr2 = A + (long)(m0 + ar2) * lda + akq;
    const uint32_t adst1 = uA + (uint32_t)(ar1 * 20 + akq) * 4;
    const uint32_t adst2 = uA + (uint32_t)(ar2 * 20 + akq) * 4;

    // ---- B loader (NN): rows tid>>5 and +8, cols (tid&31)*4
    const int brow = tid >> 5;
    const int bcol = (tid & 31) * 4;
    const float* bptr1 = B + (long)brow * ldb + n0 + bcol;
    const float* bptr2 = B + (long)(brow + 8) * ldb + n0 + bcol;
    const uint32_t bdst1 = uB + (uint32_t)(brow * BC + bcol) * 4;
    const uint32_t bdst2 = uB + (uint32_t)((brow + 8) * BC + bcol) * 4;

    float acc[4][4][4];
#pragma unroll
    for (int mt = 0; mt < 4; mt++)
#pragma unroll
        for (int nt = 0; nt < 4; nt++)
#pragma unroll
            for (int r = 0; r < 4; r++) acc[mt][nt][r] = 0.f;

    auto load_stage = [&](int buf, int k0) {
        const uint32_t ao = (uint32_t)buf * (128 * 20 * 4);
        const uint32_t bo = (uint32_t)buf * (16 * BC * 4);
        cpa16(adst1 + ao, aptr1 + k0, true);
        cpa16(adst2 + ao, aptr2 + k0, true);
        cpa16(bdst1 + bo, bptr1 + (long)k0 * ldb, true);
        cpa16(bdst2 + bo, bptr2 + (long)k0 * ldb, true);
        cpa_commit();
    };

    load_stage(0, 0);
    cpa_wait0();
    __syncthreads();

    const int nk = K >> 4;
    int buf = 0;
    for (int kt = 0; kt < nk; kt++) {
        const bool more = (kt + 1 < nk);
        if (more) load_stage(buf ^ 1, (kt + 1) << 4);

#pragma unroll
        for (int h = 0; h < 2; h++) {
            const int c = h * 8 + (lane & 3);
            uint32_t af[4][4];
            uint32_t bf[4][2];
            const float* abase = &As[buf][wm * 64 + (lane >> 2)][c];
#pragma unroll
            for (int mt = 0; mt < 4; mt++) {
                af[mt][0] = __float_as_uint(abase[(mt * 16    ) * 20    ]);
                af[mt][1] = __float_as_uint(abase[(mt * 16 + 8) * 20    ]);
                af[mt][2] = __float_as_uint(abase[(mt * 16    ) * 20 + 4]);
                af[mt][3] = __float_as_uint(abase[(mt * 16 + 8) * 20 + 4]);
            }
#pragma unroll
            for (int nt = 0; nt < 4; nt++) {
                const int nB = wn * 32 + nt * 8 + (lane >> 2);
                bf[nt][0] = __float_as_uint(Bs[buf][c][nB]);
                bf[nt][1] = __float_as_uint(Bs[buf][c + 4][nB]);
            }
#pragma unroll
            for (int mt = 0; mt < 4; mt++)
#pragma unroll
                for (int nt = 0; nt < 4; nt++)
                    mma8(acc[mt][nt], af[mt], bf[nt]);
        }

        if (more) {
            cpa_wait0();
            __syncthreads();
            buf ^= 1;
        }
    }

#pragma unroll
    for (int mt = 0; mt < 4; mt++) {
        const int r0 = m0 + wm * 64 + mt * 16 + (lane >> 2);
        const int r1 = r0 + 8;
#pragma unroll
        for (int nt = 0; nt < 4; nt++) {
            const int cc = n0 + wn * 32 + nt * 8 + (lane & 3) * 2;
            float v0 = acc[mt][nt][0], v1 = acc[mt][nt][1];
            float v2 = acc[mt][nt][2], v3 = acc[mt][nt][3];
            if (OTF) { v0 = f2tf32(v0); v1 = f2tf32(v1); v2 = f2tf32(v2); v3 = f2tf32(v3); }
            *(float2*)&C[(long)r0 * ldc + cc] = make_float2(v0, v1);
            *(float2*)&C[(long)r1 * ldc + cc] = make_float2(v2, v3);
        }
    }
}

// ---------------------------------------------------------------------------
// E = Q @ K^T fused with combine. 64x128 tile (grid 7x4x8 = 224 CTAs so all
// 148 SMs are busy; ~90 regs + 30 KB smem lets 2 CTAs co-reside), BK=16,
// 256 threads = 8 warps as 2(m)x4(n), warp tile 32x32 (2x4 m16n8k8).
// out[b,i,j] = (acc + S[b,i, j-i+399]) / 16; mask half written by setup.
// ---------------------------------------------------------------------------
__global__ __launch_bounds__(256)
void mmaE(const float* __restrict__ P, const float* __restrict__ S,
          float* __restrict__ out)
{
    __shared__ float As[2][64][20];
    __shared__ float Bs[2][128][20];

    const int tid  = threadIdx.x;
    const int lane = tid & 31;
    const int wid  = tid >> 5;      // 0..7
    const int wm   = wid >> 2;      // 0..1 -> 32-row half
    const int wn   = wid & 3;       // 0..3 -> 32-col quarter
    const int m0   = blockIdx.y * 64;    // 0..384 (7 tiles)
    const int n0   = blockIdx.x * 128;   // 0..384 (4 tiles)
    const int b    = blockIdx.z;

    const float* A = P + (long)b * SEQ * PW;        // Q
    const float* B = P + (long)b * SEQ * PW + DM;   // K

    const uint32_t uA = (uint32_t)__cvta_generic_to_shared(&As[0][0][0]);
    const uint32_t uB = (uint32_t)__cvta_generic_to_shared(&Bs[0][0][0]);

    // A loader: one quad per thread; row=tid>>2 (0..63), kq=(tid&3)*4
    const int ar  = tid >> 2;
    const int akq = (tid & 3) * 4;
    const bool aok = (m0 + ar) < SEQ;
    const float* aptr = A + (long)(aok ? (m0 + ar) : 0) * PW + akq;
    const uint32_t adst = uA + (uint32_t)(ar * 20 + akq) * 4;

    // B loader (NT): rows tid>>2 and +64
    const int br1 = tid >> 2, br2 = br1 + 64;
    const bool bok1 = (n0 + br1) < SEQ;
    const bool bok2 = (n0 + br2) < SEQ;
    const float* bptr1 = B + (long)(bok1 ? (n0 + br1) : 0) * PW + akq;
    const float* bptr2 = B + (long)(bok2 ? (n0 + br2) : 0) * PW + akq;
    const uint32_t bdst1 = uB + (uint32_t)(br1 * 20 + akq) * 4;
    const uint32_t bdst2 = uB + (uint32_t)(br2 * 20 + akq) * 4;

    float acc[2][4][4];
#pragma unroll
    for (int mt = 0; mt < 2; mt++)
#pragma unroll
        for (int nt = 0; nt < 4; nt++)
#pragma unroll
            for (int r = 0; r < 4; r++) acc[mt][nt][r] = 0.f;

    auto load_stage = [&](int buf, int k0) {
        const uint32_t ao = (uint32_t)buf * (64 * 20 * 4);
        const uint32_t bo = (uint32_t)buf * (128 * 20 * 4);
        cpa16(adst + ao,  aptr  + k0, aok);
        cpa16(bdst1 + bo, bptr1 + k0, bok1);
        cpa16(bdst2 + bo, bptr2 + k0, bok2);
        cpa_commit();
    };

    load_stage(0, 0);
    cpa_wait0();
    __syncthreads();

    const int nk = DM >> 4;   // 16
    int buf = 0;
    for (int kt = 0; kt < nk; kt++) {
        const bool more = (kt + 1 < nk);
        if (more) load_stage(buf ^ 1, (kt + 1) << 4);

#pragma unroll
        for (int h = 0; h < 2; h++) {
            const int c = h * 8 + (lane & 3);
            uint32_t af[2][4];
            uint32_t bf[4][2];
            const float* abase = &As[buf][wm * 32 + (lane >> 2)][c];
#pragma unroll
            for (int mt = 0; mt < 2; mt++) {
                af[mt][0] = __float_as_uint(abase[(mt * 16    ) * 20    ]);
                af[mt][1] = __float_as_uint(abase[(mt * 16 + 8) * 20    ]);
                af[mt][2] = __float_as_uint(abase[(mt * 16    ) * 20 + 4]);
                af[mt][3] = __float_as_uint(abase[(mt * 16 + 8) * 20 + 4]);
            }
#pragma unroll
            for (int nt = 0; nt < 4; nt++) {
                const int nB = wn * 32 + nt * 8 + (lane >> 2);
                bf[nt][0] = __float_as_uint(Bs[buf][nB][c]);
                bf[nt][1] = __float_as_uint(Bs[buf][nB][c + 4]);
            }
#pragma unroll
            for (int mt = 0; mt < 2; mt++)
#pragma unroll
                for (int nt = 0; nt < 4; nt++)
                    mma8(acc[mt][nt], af[mt], bf[nt]);
        }

        if (more) {
            cpa_wait0();
            __syncthreads();
            buf ^= 1;
        }
    }

    // ---- fused combine epilogue ----
#pragma unroll
    for (int mt = 0; mt < 2; mt++) {
        const int ibase = m0 + wm * 32 + mt * 16 + (lane >> 2);
#pragma unroll
        for (int half = 0; half < 2; half++) {
            const int i = ibase + half * 8;
            if (i >= SEQ) continue;
            const float* srow = S + (long)(b * SEQ + i) * ND2 + (399 - i);
            const long obase = (long)b * SEQ * SEQ + (long)i * SEQ;
#pragma unroll
            for (int nt = 0; nt < 4; nt++) {
                const int cc = n0 + wn * 32 + nt * 8 + (lane & 3) * 2;
                if (cc >= SEQ) continue;   // cc even, so cc+1 <= 399
                const float v0 = (acc[mt][nt][half * 2 + 0] + srow[cc])     * 0.0625f;
                const float v1 = (acc[mt][nt][half * 2 + 1] + srow[cc + 1]) * 0.0625f;
                *(float2*)&out[obase + cc] = make_float2(v0, v1);
            }
        }
    }
}

extern "C" void kernel_launch(void* const* d_in, const int* in_sizes, int n_in,
                              void* d_out, int out_size)
{
    const float* x    = (const float*)d_in[0];  // (8,400,512)
    const int*   mask = (const int*)  d_in[1];  // (8,400)
    const float* w_q  = (const float*)d_in[2];  // (512,256)
    const float* w_q2 = (const float*)d_in[3];  // (512,256)
    const float* w_k  = (const float*)d_in[4];  // (512,256)
    const float* w_k2 = (const float*)d_in[5];  // (256,256)
    const float* rel  = (const float*)d_in[6];  // (1,400,400,256)
    float* out = (float*)d_out;

    float *Xt, *Wcat, *P, *RT, *S;
    cudaGetSymbolAddress((void**)&Xt,   g_Xt);
    cudaGetSymbolAddress((void**)&Wcat, g_Wcat);
    cudaGetSymbolAddress((void**)&P,    g_P);
    cudaGetSymbolAddress((void**)&RT,   g_RT);
    cudaGetSymbolAddress((void**)&S,    g_S);

    // 1) All setup in one launch (Xt, Wcat, RT, mask half of out)
    setup_all<<<SB4, 256>>>(x, w_q, w_k, w_q2, w_k2, rel, mask,
                            Xt, Wcat, RT, out, out_size);

    // 2) P = Xt @ Wcat  (3200x768x512), output tf32-rounded
    mmaT<true><<<dim3(PW / 128, BS / 128), 256>>>(Xt, Wcat, P, SD, SD, PW, PW);

    // 3) S = P[:,512:768) @ RT  (3200x896x256), output fp32
    mmaT<false><<<dim3(ND2 / 128, BS / 128), 256>>>(P + SD, RT, S, DM, PW, ND2, ND2);

    // 4) E = Q @ K^T fused with combine (64x128 tiles, 224 CTAs)
    mmaE<<<dim3(4, 7, BATCH), 256>>>(P, S, out);
}

// round 12
// speedup vs baseline: 1.7135x; 1.1348x over previous
#include <cuda_runtime.h>
#include <cstdint>

#define SEQ 400
#define BATCH 8
#define DM 256          // d_model
#define SD 512          // source_dim
#define PW 768          // packed projection width: [Q | K | Q2W]
#define ND2 896         // delta columns padded (799 real)
#define BS (BATCH*SEQ)          // 3200
#define BSS (BATCH*SEQ*SEQ)     // 1280000

// Scratch (device globals — no allocations allowed)
__device__ float g_Xt[BS*SD];        // tf32-rounded x              (3200x512)
__device__ float g_Wcat[SD*PW];      // [w_q | w_k | w_q2@w_k2^T]   (512x768) tf32
__device__ float g_P[BS*PW];         // Xt @ Wcat                   (3200x768) tf32
__device__ float g_RT[DM*ND2];       // R^T: [d][delta+399]         (256x896) tf32
__device__ float g_S[BS*ND2];        // P[:,512:768] @ RT           (3200x896) fp32

// ---------------------------------------------------------------------------
__device__ __forceinline__ float f2tf32(float f) {
    uint32_t u;
    asm("cvt.rna.tf32.f32 %0, %1;" : "=r"(u) : "f"(f));
    return __uint_as_float(u);
}

__device__ __forceinline__ void mma8(float c[4], const uint32_t a[4], const uint32_t b[2]) {
    asm volatile("mma.sync.aligned.m16n8k8.row.col.f32.tf32.tf32.f32 "
        "{%0,%1,%2,%3}, {%4,%5,%6,%7}, {%8,%9}, {%0,%1,%2,%3};"
        : "+f"(c[0]), "+f"(c[1]), "+f"(c[2]), "+f"(c[3])
        : "r"(a[0]), "r"(a[1]), "r"(a[2]), "r"(a[3]), "r"(b[0]), "r"(b[1]));
}

__device__ __forceinline__ void cpa16(uint32_t dst, const float* src, bool p) {
    asm volatile("cp.async.cg.shared.global [%0], [%1], 16, %2;"
                 :: "r"(dst), "l"(src), "r"(p ? 16 : 0));
}
__device__ __forceinline__ void cpa_commit() {
    asm volatile("cp.async.commit_group;");
}
__device__ __forceinline__ void cpa_wait0() {
    asm volatile("cp.async.wait_group 0;");
}

// ---------------------------------------------------------------------------
// Fused setup kernel — all sections independent, one launch, 256 threads.
// ---------------------------------------------------------------------------
#define SB0 1600
#define SB1 (SB0 + 128)
#define SB2 (SB1 + 112)
#define SB3 (SB2 + 32)
#define SB4 (SB3 + 1250)

__global__ __launch_bounds__(256)
void setup_all(const float* __restrict__ x,
               const float* __restrict__ wq, const float* __restrict__ wk,
               const float* __restrict__ wq2, const float* __restrict__ wk2,
               const float* __restrict__ rel, const int* __restrict__ mask,
               float* __restrict__ Xt, float* __restrict__ Wcat,
               float* __restrict__ RT, float* __restrict__ out, int out_size)
{
    __shared__ float sh[2176 * 2];
    const int blk = blockIdx.x;
    const int tid = threadIdx.x;

    if (blk < SB0) {
        const int idx = blk * 256 + tid;
        float4 v = ((const float4*)x)[idx];
        v.x = f2tf32(v.x); v.y = f2tf32(v.y); v.z = f2tf32(v.z); v.w = f2tf32(v.w);
        ((float4*)Xt)[idx] = v;
    } else if (blk < SB1) {
        const int idx = (blk - SB0) * 256 + tid;
        const int row = idx / (DM / 4);
        const int c4  = idx % (DM / 4);
        float4 q = ((const float4*)wq)[idx];
        float4 k = ((const float4*)wk)[idx];
        q.x = f2tf32(q.x); q.y = f2tf32(q.y); q.z = f2tf32(q.z); q.w = f2tf32(q.w);
        k.x = f2tf32(k.x); k.y = f2tf32(k.y); k.z = f2tf32(k.z); k.w = f2tf32(k.w);
        ((float4*)(Wcat + (long)row * PW))[c4] = q;
        ((float4*)(Wcat + (long)row * PW + DM))[c4] = k;
    } else if (blk < SB2) {
        float (*t)[65] = (float(*)[65])sh;
        const int blk2 = blk - SB1;
        const int m0 = (blk2 % 28) * 32;
        const int d0 = (blk2 / 28) * 64;
        const int dl = tid & 63, mb = tid >> 6;
#pragma unroll
        for (int it = 0; it < 8; it++) {
            const int ml = mb * 8 + it;
            const int m = m0 + ml;
            float v = 0.f;
            if (m <= 798) {
                const int delta = m - 399;
                const long off = (delta >= 0) ? (long)delta * DM
                                              : (long)(-delta) * SEQ * DM;
                v = f2tf32(rel[off + d0 + dl]);
            }
            t[ml][dl] = v;
        }
        __syncthreads();
        const int ml2 = tid & 31, db = tid >> 5;
#pragma unroll
        for (int it = 0; it < 8; it++) {
            const int dl2 = db + it * 8;
            RT[(long)(d0 + dl2) * ND2 + m0 + ml2] = t[ml2][dl2];
        }
    } else if (blk < SB3) {
        float (*As)[68] = (float(*)[68])sh;
        float (*Bs)[68] = (float(*)[68])(sh + 16 * 68);
        const int blk2 = blk - SB2;
        const int m0 = (blk2 >> 2) * 64, n0 = (blk2 & 3) * 64;
        const int tx = tid & 15, ty = tid >> 4;
        const int ar = tid >> 2, ak = (tid & 3) * 4;
        float acc[4][4] = {};
        for (int k0 = 0; k0 < DM; k0 += 16) {
            float4 v = *(const float4*)(wq2 + (long)(m0 + ar) * DM + k0 + ak);
            As[ak][ar] = v.x; As[ak+1][ar] = v.y; As[ak+2][ar] = v.z; As[ak+3][ar] = v.w;
            float4 w = *(const float4*)(wk2 + (long)(n0 + ar) * DM + k0 + ak);
            Bs[ak][ar] = w.x; Bs[ak+1][ar] = w.y; Bs[ak+2][ar] = w.z; Bs[ak+3][ar] = w.w;
            __syncthreads();
#pragma unroll
            for (int kk = 0; kk < 16; kk++) {
                const float4 a = *(const float4*)&As[kk][ty * 4];
                const float4 b = *(const float4*)&Bs[kk][tx * 4];
                acc[0][0]+=a.x*b.x; acc[0][1]+=a.x*b.y; acc[0][2]+=a.x*b.z; acc[0][3]+=a.x*b.w;
                acc[1][0]+=a.y*b.x; acc[1][1]+=a.y*b.y; acc[1][2]+=a.y*b.z; acc[1][3]+=a.y*b.w;
                acc[2][0]+=a.z*b.x; acc[2][1]+=a.z*b.y; acc[2][2]+=a.z*b.z; acc[2][3]+=a.z*b.w;
                acc[3][0]+=a.w*b.x; acc[3][1]+=a.w*b.y; acc[3][2]+=a.w*b.z; acc[3][3]+=a.w*b.w;
            }
            __syncthreads();
        }
#pragma unroll
        for (int r = 0; r < 4; r++)
#pragma unroll
            for (int c = 0; c < 4; c++)
                Wcat[(long)(m0 + ty*4 + r) * PW + SD + n0 + tx*4 + c] = f2tf32(acc[r][c]);
    } else if (blk < SB4) {
        if (out_size < 2 * BSS) return;
        const int i4 = (blk - SB3) * 256 + tid;
        const long idx = (long)i4 * 4;
        if (idx >= BSS) return;
        const int j = (int)(idx % SEQ);
        const int bi = (int)(idx / SEQ);
        const int i = bi % SEQ, b = bi / SEQ;
        const float mi = (float)mask[b * SEQ + i];
        float4 o;
        o.x = mi * mask[b * SEQ + j];
        o.y = mi * mask[b * SEQ + j + 1];
        o.z = mi * mask[b * SEQ + j + 2];
        o.w = mi * mask[b * SEQ + j + 3];
        *(float4*)&out[BSS + idx] = o;
    }
}

// ---------------------------------------------------------------------------
// tf32 NN GEMM, 128x128 block, BK=32, 256 threads (8 warps, 64x32 warp
// tiles). Two-stage cp.async (R9 discipline), dynamic smem, pad-36 A rows
// (conflict-free fragment reads), pad-136 B rows. Used for P and S.
// Requires M%128==0, N%128==0, K%32==0. OTF: tf32-round C on store.
// ---------------------------------------------------------------------------
template <bool OTF>
__global__ __launch_bounds__(256)
void mmaT(const float* __restrict__ A, const float* __restrict__ B,
          float* __restrict__ C, int K, int lda, int ldb, int ldc)
{
    constexpr int ASZ = 128 * 36;   // one stage of A
    constexpr int BSZ = 32 * 136;   // one stage of B
    extern __shared__ float sh[];
    float* Asb = sh;
    float* Bsb = sh + 2 * ASZ;

    const int tid  = threadIdx.x;
    const int lane = tid & 31;
    const int wid  = tid >> 5;
    const int wm   = wid >> 2;
    const int wn   = wid & 3;
    const int m0   = blockIdx.y * 128;
    const int n0   = blockIdx.x * 128;

    const uint32_t uA = (uint32_t)__cvta_generic_to_shared(Asb);
    const uint32_t uB = (uint32_t)__cvta_generic_to_shared(Bsb);

    // A loader: 4 quads; rows (tid>>3)+{0,32,64,96}, col (tid&7)*4
    const int arow = tid >> 3;
    const int acol = (tid & 7) * 4;
    const float* aptr = A + (long)(m0 + arow) * lda + acol;
    const uint32_t adst = uA + (uint32_t)(arow * 36 + acol) * 4;

    // B loader: 4 quads; rows (tid>>5)+{0,8,16,24}, col (tid&31)*4
    const int brow = tid >> 5;
    const int bcol = (tid & 31) * 4;
    const float* bptr = B + (long)brow * ldb + n0 + bcol;
    const uint32_t bdst = uB + (uint32_t)(brow * 136 + bcol) * 4;

    float acc[4][4][4];
#pragma unroll
    for (int mt = 0; mt < 4; mt++)
#pragma unroll
        for (int nt = 0; nt < 4; nt++)
#pragma unroll
            for (int r = 0; r < 4; r++) acc[mt][nt][r] = 0.f;

    auto load_stage = [&](int buf, int k0) {
        const uint32_t ao = (uint32_t)buf * (ASZ * 4);
        const uint32_t bo = (uint32_t)buf * (BSZ * 4);
#pragma unroll
        for (int j = 0; j < 4; j++)
            cpa16(adst + ao + (uint32_t)(j * 32 * 36) * 4,
                  aptr + (long)(j * 32) * lda + k0, true);
#pragma unroll
        for (int j = 0; j < 4; j++)
            cpa16(bdst + bo + (uint32_t)(j * 8 * 136) * 4,
                  bptr + (long)(k0 + j * 8) * ldb, true);
        cpa_commit();
    };

    load_stage(0, 0);
    cpa_wait0();
    __syncthreads();

    const int nk = K >> 5;
    int buf = 0;
    for (int kt = 0; kt < nk; kt++) {
        const bool more = (kt + 1 < nk);
        if (more) load_stage(buf ^ 1, (kt + 1) << 5);

        const float* Astage = Asb + buf * ASZ;
        const float* Bstage = Bsb + buf * BSZ;
#pragma unroll
        for (int h = 0; h < 4; h++) {
            const int c = h * 8 + (lane & 3);
            uint32_t af[4][4];
            uint32_t bf[4][2];
            const float* abase = Astage + (wm * 64 + (lane >> 2)) * 36 + c;
#pragma unroll
            for (int mt = 0; mt < 4; mt++) {
                af[mt][0] = __float_as_uint(abase[(mt * 16    ) * 36    ]);
                af[mt][1] = __float_as_uint(abase[(mt * 16 + 8) * 36    ]);
                af[mt][2] = __float_as_uint(abase[(mt * 16    ) * 36 + 4]);
                af[mt][3] = __float_as_uint(abase[(mt * 16 + 8) * 36 + 4]);
            }
#pragma unroll
            for (int nt = 0; nt < 4; nt++) {
                const int nB = wn * 32 + nt * 8 + (lane >> 2);
                bf[nt][0] = __float_as_uint(Bstage[(c    ) * 136 + nB]);
                bf[nt][1] = __float_as_uint(Bstage[(c + 4) * 136 + nB]);
            }
#pragma unroll
            for (int mt = 0; mt < 4; mt++)
#pragma unroll
                for (int nt = 0; nt < 4; nt++)
                    mma8(acc[mt][nt], af[mt], bf[nt]);
        }

        if (more) {
            cpa_wait0();
            __syncthreads();
            buf ^= 1;
        }
    }

#pragma unroll
    for (int mt = 0; mt < 4; mt++) {
        const int r0 = m0 + wm * 64 + mt * 16 + (lane >> 2);
        const int r1 = r0 + 8;
#pragma unroll
        for (int nt = 0; nt < 4; nt++) {
            const int cc = n0 + wn * 32 + nt * 8 + (lane & 3) * 2;
            float v0 = acc[mt][nt][0], v1 = acc[mt][nt][1];
            float v2 = acc[mt][nt][2], v3 = acc[mt][nt][3];
            if (OTF) { v0 = f2tf32(v0); v1 = f2tf32(v1); v2 = f2tf32(v2); v3 = f2tf32(v3); }
            *(float2*)&C[(long)r0 * ldc + cc] = make_float2(v0, v1);
            *(float2*)&C[(long)r1 * ldc + cc] = make_float2(v2, v3);
        }
    }
}

// ---------------------------------------------------------------------------
// E = Q @ K^T fused with combine. 64x128 tile, BK=32, 256 threads (8 warps
// 2x4, warp tile 32x32). The CTA's diagonal S window (64 rows x 144 cols)
// is prefetched into smem via cp.async chunks bundled with the mainloop's
// commit groups — S-read latency hidden behind mma. Epilogue reads LDS.
// ---------------------------------------------------------------------------
__global__ __launch_bounds__(256)
void mmaE(const float* __restrict__ P, const float* __restrict__ S,
          float* __restrict__ out)
{
    constexpr int ASZ = 64 * 36;
    constexpr int BSZ = 128 * 36;
    constexpr int SROW = 148;           // 144 data + 4 pad
    extern __shared__ float sh[];
    float* Asb = sh;                    // 2 stages
    float* Bsb = sh + 2 * ASZ;          // 2 stages
    float* Ss  = sh + 2 * ASZ + 2 * BSZ;// 64 x 148

    const int tid  = threadIdx.x;
    const int lane = tid & 31;
    const int wid  = tid >> 5;
    const int wm   = wid >> 2;          // 0..1 -> 32-row half
    const int wn   = wid & 3;           // 0..3 -> 32-col quarter
    const int m0   = blockIdx.y * 64;
    const int n0   = blockIdx.x * 128;
    const int b    = blockIdx.z;
    const int w0   = n0 - m0 + 399;

    const float* A = P + (long)b * SEQ * PW;        // Q
    const float* B = P + (long)b * SEQ * PW + DM;   // K

    const uint32_t uA = (uint32_t)__cvta_generic_to_shared(Asb);
    const uint32_t uB = (uint32_t)__cvta_generic_to_shared(Bsb);
    const uint32_t uS = (uint32_t)__cvta_generic_to_shared(Ss);

    // A loader: 2 quads; rows (tid>>3)+{0,32}, col (tid&7)*4
    const int arow = tid >> 3;
    const int acol = (tid & 7) * 4;
    const bool aok0 = (m0 + arow) < SEQ;
    const bool aok1 = (m0 + arow + 32) < SEQ;
    const float* aptr = A + (long)(m0 + arow) * PW + acol;
    const uint32_t adst = uA + (uint32_t)(arow * 36 + acol) * 4;

    // B loader: 4 quads; rows (tid>>3)+{0,32,64,96}
    bool bok[4];
#pragma unroll
    for (int j = 0; j < 4; j++) bok[j] = (n0 + arow + j * 32) < SEQ;
    const float* bptr = B + (long)(n0 + arow) * PW + acol;
    const uint32_t bdst = uB + (uint32_t)(arow * 36 + acol) * 4;

    float acc[2][4][4];
#pragma unroll
    for (int mt = 0; mt < 2; mt++)
#pragma unroll
        for (int nt = 0; nt < 4; nt++)
#pragma unroll
            for (int r = 0; r < 4; r++) acc[mt][nt][r] = 0.f;

    // S prefetch: 64 rows x 36 quads = 2304 quads, 8 chunks of 288
    auto s_chunk = [&](int ci) {
#pragma unroll
        for (int part = 0; part < 2; part++) {
            const int t = part * 256 + tid;
            if (part == 1 && tid >= 32) break;
            const int gq = ci * 288 + t;         // < 2304
            const int r = gq / 36;
            const int q = gq % 36;
            const int base = (w0 - r) & ~3;
            const int col = base + q * 4;
            const bool ok = ((m0 + r) < SEQ) && (col >= 0) && (col < 893);
            const float* src = S + (long)(b * SEQ + m0 + r) * ND2 + col;
            cpa16(uS + (uint32_t)(r * SROW + q * 4) * 4, src, ok);
        }
    };

    auto load_stage = [&](int buf, int k0, int ci) {
        const uint32_t ao = (uint32_t)buf * (ASZ * 4);
        const uint32_t bo = (uint32_t)buf * (BSZ * 4);
        cpa16(adst + ao, aptr + k0, aok0);
        cpa16(adst + ao + (uint32_t)(32 * 36) * 4, aptr + (long)32 * PW + k0, aok1);
#pragma unroll
        for (int j = 0; j < 4; j++)
            cpa16(bdst + bo + (uint32_t)(j * 32 * 36) * 4,
                  bptr + (long)(j * 32) * PW + k0, bok[j]);
        s_chunk(ci);
        cpa_commit();
    };

    const int nk = DM >> 5;   // 8
    load_stage(0, 0, 0);
    cpa_wait0();
    __syncthreads();

    int buf = 0;
    for (int kt = 0; kt < nk; kt++) {
        const bool more = (kt + 1 < nk);
        if (more) load_stage(buf ^ 1, (kt + 1) << 5, kt + 1);

        const float* Astage = Asb + buf * ASZ;
        const float* Bstage = Bsb + buf * BSZ;
#pragma unroll
        for (int h = 0; h < 4; h++) {
            const int c = h * 8 + (lane & 3);
            uint32_t af[2][4];
            uint32_t bf[4][2];
            const float* abase = Astage + (wm * 32 + (lane >> 2)) * 36 + c;
#pragma unroll
            for (int mt = 0; mt < 2; mt++) {
                af[mt][0] = __float_as_uint(abase[(mt * 16    ) * 36    ]);
                af[mt][1] = __float_as_uint(abase[(mt * 16 + 8) * 36    ]);
                af[mt][2] = __float_as_uint(abase[(mt * 16    ) * 36 + 4]);
                af[mt][3] = __float_as_uint(abase[(mt * 16 + 8) * 36 + 4]);
            }
#pragma unroll
            for (int nt = 0; nt < 4; nt++) {
                const int nB = wn * 32 + nt * 8 + (lane >> 2);
                bf[nt][0] = __float_as_uint(Bstage[nB * 36 + c]);
                bf[nt][1] = __float_as_uint(Bstage[nB * 36 + c + 4]);
            }
#pragma unroll
            for (int mt = 0; mt < 2; mt++)
#pragma unroll
                for (int nt = 0; nt < 4; nt++)
                    mma8(acc[mt][nt], af[mt], bf[nt]);
        }

        if (more) {
            cpa_wait0();
            __syncthreads();
            buf ^= 1;
        }
    }

    // ---- fused combine epilogue (S from smem) ----
#pragma unroll
    for (int mt = 0; mt < 2; mt++) {
        const int ibase = m0 + wm * 32 + mt * 16 + (lane >> 2);
#pragma unroll
        for (int half = 0; half < 2; half++) {
            const int i = ibase + half * 8;
            if (i >= SEQ) continue;
            const int r = i - m0;
            const float* srow = Ss + r * SROW + ((w0 - r) & 3) - n0;
            const long obase = (long)b * SEQ * SEQ + (long)i * SEQ;
#pragma unroll
            for (int nt = 0; nt < 4; nt++) {
                const int cc = n0 + wn * 32 + nt * 8 + (lane & 3) * 2;
                if (cc >= SEQ) continue;   // cc even, so cc+1 <= 399
                const float v0 = (acc[mt][nt][half * 2 + 0] + srow[cc])     * 0.0625f;
                const float v1 = (acc[mt][nt][half * 2 + 1] + srow[cc + 1]) * 0.0625f;
                *(float2*)&out[obase + cc] = make_float2(v0, v1);
            }
        }
    }
}

extern "C" void kernel_launch(void* const* d_in, const int* in_sizes, int n_in,
                              void* d_out, int out_size)
{
    const float* x    = (const float*)d_in[0];  // (8,400,512)
    const int*   mask = (const int*)  d_in[1];  // (8,400)
    const float* w_q  = (const float*)d_in[2];  // (512,256)
    const float* w_q2 = (const float*)d_in[3];  // (512,256)
    const float* w_k  = (const float*)d_in[4];  // (512,256)
    const float* w_k2 = (const float*)d_in[5];  // (256,256)
    const float* rel  = (const float*)d_in[6];  // (1,400,400,256)
    float* out = (float*)d_out;

    float *Xt, *Wcat, *P, *RT, *S;
    cudaGetSymbolAddress((void**)&Xt,   g_Xt);
    cudaGetSymbolAddress((void**)&Wcat, g_Wcat);
    cudaGetSymbolAddress((void**)&P,    g_P);
    cudaGetSymbolAddress((void**)&RT,   g_RT);
    cudaGetSymbolAddress((void**)&S,    g_S);

    const int smemT = (2 * 128 * 36 + 2 * 32 * 136) * 4;            // 71680
    const int smemE = (2 * 64 * 36 + 2 * 128 * 36 + 64 * 148) * 4;  // 93184
    cudaFuncSetAttribute(mmaT<true>,
        cudaFuncAttributeMaxDynamicSharedMemorySize, smemT);
    cudaFuncSetAttribute(mmaT<false>,
        cudaFuncAttributeMaxDynamicSharedMemorySize, smemT);
    cudaFuncSetAttribute(mmaE,
        cudaFuncAttributeMaxDynamicSharedMemorySize, smemE);

    // 1) All setup in one launch (Xt, Wcat, RT, mask half of out)
    setup_all<<<SB4, 256>>>(x, w_q, w_k, w_q2, w_k2, rel, mask,
                            Xt, Wcat, RT, out, out_size);

    // 2) P = Xt @ Wcat  (3200x768x512), output tf32-rounded
    mmaT<true><<<dim3(PW / 128, BS / 128), 256, smemT>>>(
        Xt, Wcat, P, SD, SD, PW, PW);

    // 3) S = P[:,512:768) @ RT  (3200x896x256), output fp32
    mmaT<false><<<dim3(ND2 / 128, BS / 128), 256, smemT>>>(
        P + SD, RT, S, DM, PW, ND2, ND2);

    // 4) E = Q @ K^T fused with combine + smem S window (224 CTAs)
    mmaE<<<dim3(4, 7, BATCH), 256, smemE>>>(P, S, out);
}

// round 13
// speedup vs baseline: 1.7628x; 1.0287x over previous
#include <cuda_runtime.h>
#include <cstdint>

#define SEQ 400
#define BATCH 8
#define DM 256          // d_model
#define SD 512          // source_dim
#define PW 768          // packed projection width: [Q | K | Q2W]
#define ND2 896         // delta columns padded (799 real)
#define BS (BATCH*SEQ)          // 3200
#define BSS (BATCH*SEQ*SEQ)     // 1280000

// Scratch (device globals — no allocations allowed)
__device__ float g_Xt[BS*SD];        // tf32-rounded x              (3200x512)
__device__ float g_Wcat[SD*PW];      // [w_q | w_k | w_q2@w_k2^T]   (512x768) tf32
__device__ float g_P[BS*PW];         // Xt @ Wcat                   (3200x768) tf32
__device__ float g_RT[DM*ND2];       // R^T: [d][delta+399]         (256x896) tf32
__device__ float g_S[BS*ND2];        // P[:,512:768] @ RT           (3200x896) fp32

// ---------------------------------------------------------------------------
__device__ __forceinline__ float f2tf32(float f) {
    uint32_t u;
    asm("cvt.rna.tf32.f32 %0, %1;" : "=r"(u) : "f"(f));
    return __uint_as_float(u);
}

__device__ __forceinline__ void mma8(float c[4], const uint32_t a[4], const uint32_t b[2]) {
    asm volatile("mma.sync.aligned.m16n8k8.row.col.f32.tf32.tf32.f32 "
        "{%0,%1,%2,%3}, {%4,%5,%6,%7}, {%8,%9}, {%0,%1,%2,%3};"
        : "+f"(c[0]), "+f"(c[1]), "+f"(c[2]), "+f"(c[3])
        : "r"(a[0]), "r"(a[1]), "r"(a[2]), "r"(a[3]), "r"(b[0]), "r"(b[1]));
}

__device__ __forceinline__ void cpa16(uint32_t dst, const float* src, bool p) {
    asm volatile("cp.async.cg.shared.global [%0], [%1], 16, %2;"
                 :: "r"(dst), "l"(src), "r"(p ? 16 : 0));
}
__device__ __forceinline__ void cpa_commit() {
    asm volatile("cp.async.commit_group;");
}
__device__ __forceinline__ void cpa_wait0() {
    asm volatile("cp.async.wait_group 0;");
}

// ---------------------------------------------------------------------------
// Fused setup kernel — all sections independent, one launch, 256 threads.
// ---------------------------------------------------------------------------
#define SB0 1600
#define SB1 (SB0 + 128)
#define SB2 (SB1 + 112)
#define SB3 (SB2 + 32)
#define SB4 (SB3 + 1250)

__global__ __launch_bounds__(256)
void setup_all(const float* __restrict__ x,
               const float* __restrict__ wq, const float* __restrict__ wk,
               const float* __restrict__ wq2, const float* __restrict__ wk2,
               const float* __restrict__ rel, const int* __restrict__ mask,
               float* __restrict__ Xt, float* __restrict__ Wcat,
               float* __restrict__ RT, float* __restrict__ out, int out_size)
{
    __shared__ float sh[2176 * 2];
    const int blk = blockIdx.x;
    const int tid = threadIdx.x;

    if (blk < SB0) {
        const int idx = blk * 256 + tid;
        float4 v = ((const float4*)x)[idx];
        v.x = f2tf32(v.x); v.y = f2tf32(v.y); v.z = f2tf32(v.z); v.w = f2tf32(v.w);
        ((float4*)Xt)[idx] = v;
    } else if (blk < SB1) {
        const int idx = (blk - SB0) * 256 + tid;
        const int row = idx / (DM / 4);
        const int c4  = idx % (DM / 4);
        float4 q = ((const float4*)wq)[idx];
        float4 k = ((const float4*)wk)[idx];
        q.x = f2tf32(q.x); q.y = f2tf32(q.y); q.z = f2tf32(q.z); q.w = f2tf32(q.w);
        k.x = f2tf32(k.x); k.y = f2tf32(k.y); k.z = f2tf32(k.z); k.w = f2tf32(k.w);
        ((float4*)(Wcat + (long)row * PW))[c4] = q;
        ((float4*)(Wcat + (long)row * PW + DM))[c4] = k;
    } else if (blk < SB2) {
        float (*t)[65] = (float(*)[65])sh;
        const int blk2 = blk - SB1;
        const int m0 = (blk2 % 28) * 32;
        const int d0 = (blk2 / 28) * 64;
        const int dl = tid & 63, mb = tid >> 6;
#pragma unroll
        for (int it = 0; it < 8; it++) {
            const int ml = mb * 8 + it;
            const int m = m0 + ml;
            float v = 0.f;
            if (m <= 798) {
                const int delta = m - 399;
                const long off = (delta >= 0) ? (long)delta * DM
                                              : (long)(-delta) * SEQ * DM;
                v = f2tf32(rel[off + d0 + dl]);
            }
            t[ml][dl] = v;
        }
        __syncthreads();
        const int ml2 = tid & 31, db = tid >> 5;
#pragma unroll
        for (int it = 0; it < 8; it++) {
            const int dl2 = db + it * 8;
            RT[(long)(d0 + dl2) * ND2 + m0 + ml2] = t[ml2][dl2];
        }
    } else if (blk < SB3) {
        float (*As)[68] = (float(*)[68])sh;
        float (*Bs)[68] = (float(*)[68])(sh + 16 * 68);
        const int blk2 = blk - SB2;
        const int m0 = (blk2 >> 2) * 64, n0 = (blk2 & 3) * 64;
        const int tx = tid & 15, ty = tid >> 4;
        const int ar = tid >> 2, ak = (tid & 3) * 4;
        float acc[4][4] = {};
        for (int k0 = 0; k0 < DM; k0 += 16) {
            float4 v = *(const float4*)(wq2 + (long)(m0 + ar) * DM + k0 + ak);
            As[ak][ar] = v.x; As[ak+1][ar] = v.y; As[ak+2][ar] = v.z; As[ak+3][ar] = v.w;
            float4 w = *(const float4*)(wk2 + (long)(n0 + ar) * DM + k0 + ak);
            Bs[ak][ar] = w.x; Bs[ak+1][ar] = w.y; Bs[ak+2][ar] = w.z; Bs[ak+3][ar] = w.w;
            __syncthreads();
#pragma unroll
            for (int kk = 0; kk < 16; kk++) {
                const float4 a = *(const float4*)&As[kk][ty * 4];
                const float4 b = *(const float4*)&Bs[kk][tx * 4];
                acc[0][0]+=a.x*b.x; acc[0][1]+=a.x*b.y; acc[0][2]+=a.x*b.z; acc[0][3]+=a.x*b.w;
                acc[1][0]+=a.y*b.x; acc[1][1]+=a.y*b.y; acc[1][2]+=a.y*b.z; acc[1][3]+=a.y*b.w;
                acc[2][0]+=a.z*b.x; acc[2][1]+=a.z*b.y; acc[2][2]+=a.z*b.z; acc[2][3]+=a.z*b.w;
                acc[3][0]+=a.w*b.x; acc[3][1]+=a.w*b.y; acc[3][2]+=a.w*b.z; acc[3][3]+=a.w*b.w;
            }
            __syncthreads();
        }
#pragma unroll
        for (int r = 0; r < 4; r++)
#pragma unroll
            for (int c = 0; c < 4; c++)
                Wcat[(long)(m0 + ty*4 + r) * PW + SD + n0 + tx*4 + c] = f2tf32(acc[r][c]);
    } else if (blk < SB4) {
        if (out_size < 2 * BSS) return;
        const int i4 = (blk - SB3) * 256 + tid;
        const long idx = (long)i4 * 4;
        if (idx >= BSS) return;
        const int j = (int)(idx % SEQ);
        const int bi = (int)(idx / SEQ);
        const int i = bi % SEQ, b = bi / SEQ;
        const float mi = (float)mask[b * SEQ + i];
        float4 o;
        o.x = mi * mask[b * SEQ + j];
        o.y = mi * mask[b * SEQ + j + 1];
        o.z = mi * mask[b * SEQ + j + 2];
        o.w = mi * mask[b * SEQ + j + 3];
        *(float4*)&out[BSS + idx] = o;
    }
}

// ---------------------------------------------------------------------------
// tf32 NN GEMM, 64x128 tile (2x grid size => 2 CTAs/SM), BK=32, 256 threads
// (8 warps as 2(m) x 4(n), warp tile 32x32). Two-stage cp.async +
// register-level fragment double-buffering (load h+1 frags during h mmas).
// Requires M%64==0, N%128==0, K%32==0. OTF: tf32-round C on store.
// ---------------------------------------------------------------------------
template <bool OTF>
__global__ __launch_bounds__(256, 2)
void mmaT(const float* __restrict__ A, const float* __restrict__ B,
          float* __restrict__ C, int K, int lda, int ldb, int ldc)
{
    constexpr int ASZ = 64 * 36;    // one stage of A
    constexpr int BSZ = 32 * 136;   // one stage of B
    extern __shared__ float sh[];
    float* Asb = sh;
    float* Bsb = sh + 2 * ASZ;

    const int tid  = threadIdx.x;
    const int lane = tid & 31;
    const int wid  = tid >> 5;
    const int wm   = wid >> 2;      // 0..1 -> 32-row half
    const int wn   = wid & 3;       // 0..3 -> 32-col quarter
    const int m0   = blockIdx.y * 64;
    const int n0   = blockIdx.x * 128;

    const uint32_t uA = (uint32_t)__cvta_generic_to_shared(Asb);
    const uint32_t uB = (uint32_t)__cvta_generic_to_shared(Bsb);

    // A loader: 2 quads; rows (tid>>3)+{0,32}, col (tid&7)*4
    const int arow = tid >> 3;
    const int acol = (tid & 7) * 4;
    const float* aptr = A + (long)(m0 + arow) * lda + acol;
    const uint32_t adst = uA + (uint32_t)(arow * 36 + acol) * 4;

    // B loader: 4 quads; rows (tid>>5)+{0,8,16,24}, col (tid&31)*4
    const int brow = tid >> 5;
    const int bcol = (tid & 31) * 4;
    const float* bptr = B + (long)brow * ldb + n0 + bcol;
    const uint32_t bdst = uB + (uint32_t)(brow * 136 + bcol) * 4;

    float acc[2][4][4];
#pragma unroll
    for (int mt = 0; mt < 2; mt++)
#pragma unroll
        for (int nt = 0; nt < 4; nt++)
#pragma unroll
            for (int r = 0; r < 4; r++) acc[mt][nt][r] = 0.f;

    auto load_stage = [&](int buf, int k0) {
        const uint32_t ao = (uint32_t)buf * (ASZ * 4);
        const uint32_t bo = (uint32_t)buf * (BSZ * 4);
        cpa16(adst + ao, aptr + k0, true);
        cpa16(adst + ao + (uint32_t)(32 * 36) * 4, aptr + (long)32 * lda + k0, true);
#pragma unroll
        for (int j = 0; j < 4; j++)
            cpa16(bdst + bo + (uint32_t)(j * 8 * 136) * 4,
                  bptr + (long)(k0 + j * 8) * ldb, true);
        cpa_commit();
    };

    load_stage(0, 0);
    cpa_wait0();
    __syncthreads();

    const int nk = K >> 5;
    int buf = 0;
    for (int kt = 0; kt < nk; kt++) {
        const bool more = (kt + 1 < nk);
        if (more) load_stage(buf ^ 1, (kt + 1) << 5);

        const float* Astage = Asb + buf * ASZ;
        const float* Bstage = Bsb + buf * BSZ;

        uint32_t af[2][2][4];   // [frag buffer][mt][reg]
        uint32_t bf[2][4][2];   // [frag buffer][nt][reg]
        auto ldfrag = [&](int h, int fb) {
            const int c = h * 8 + (lane & 3);
            const float* abase = Astage + (wm * 32 + (lane >> 2)) * 36 + c;
#pragma unroll
            for (int mt = 0; mt < 2; mt++) {
                af[fb][mt][0] = __float_as_uint(abase[(mt * 16    ) * 36    ]);
                af[fb][mt][1] = __float_as_uint(abase[(mt * 16 + 8) * 36    ]);
                af[fb][mt][2] = __float_as_uint(abase[(mt * 16    ) * 36 + 4]);
                af[fb][mt][3] = __float_as_uint(abase[(mt * 16 + 8) * 36 + 4]);
            }
#pragma unroll
            for (int nt = 0; nt < 4; nt++) {
                const int nB = wn * 32 + nt * 8 + (lane >> 2);
                bf[fb][nt][0] = __float_as_uint(Bstage[(c    ) * 136 + nB]);
                bf[fb][nt][1] = __float_as_uint(Bstage[(c + 4) * 136 + nB]);
            }
        };

        ldfrag(0, 0);
#pragma unroll
        for (int h = 0; h < 4; h++) {
            const int cu = h & 1;
            if (h < 3) ldfrag(h + 1, cu ^ 1);
#pragma unroll
            for (int mt = 0; mt < 2; mt++)
#pragma unroll
                for (int nt = 0; nt < 4; nt++)
                    mma8(acc[mt][nt], af[cu][mt], bf[cu][nt]);
        }

        if (more) {
            cpa_wait0();
            __syncthreads();
            buf ^= 1;
        }
    }

#pragma unroll
    for (int mt = 0; mt < 2; mt++) {
        const int r0 = m0 + wm * 32 + mt * 16 + (lane >> 2);
        const int r1 = r0 + 8;
#pragma unroll
        for (int nt = 0; nt < 4; nt++) {
            const int cc = n0 + wn * 32 + nt * 8 + (lane & 3) * 2;
            float v0 = acc[mt][nt][0], v1 = acc[mt][nt][1];
            float v2 = acc[mt][nt][2], v3 = acc[mt][nt][3];
            if (OTF) { v0 = f2tf32(v0); v1 = f2tf32(v1); v2 = f2tf32(v2); v3 = f2tf32(v3); }
            *(float2*)&C[(long)r0 * ldc + cc] = make_float2(v0, v1);
            *(float2*)&C[(long)r1 * ldc + cc] = make_float2(v2, v3);
        }
    }
}

// ---------------------------------------------------------------------------
// E = Q @ K^T fused with combine. 64x128 tile, BK=32, 8 warps 2x4 (warp
// 32x32). S diagonal window prefetched into smem alongside mainloop stages;
// register-level fragment double-buffering in the mma loop.
// ---------------------------------------------------------------------------
__global__ __launch_bounds__(256, 2)
void mmaE(const float* __restrict__ P, const float* __restrict__ S,
          float* __restrict__ out)
{
    constexpr int ASZ = 64 * 36;
    constexpr int BSZ = 128 * 36;
    constexpr int SROW = 148;           // 144 data + 4 pad
    extern __shared__ float sh[];
    float* Asb = sh;                    // 2 stages
    float* Bsb = sh + 2 * ASZ;          // 2 stages
    float* Ss  = sh + 2 * ASZ + 2 * BSZ;// 64 x 148

    const int tid  = threadIdx.x;
    const int lane = tid & 31;
    const int wid  = tid >> 5;
    const int wm   = wid >> 2;
    const int wn   = wid & 3;
    const int m0   = blockIdx.y * 64;
    const int n0   = blockIdx.x * 128;
    const int b    = blockIdx.z;
    const int w0   = n0 - m0 + 399;

    const float* A = P + (long)b * SEQ * PW;        // Q
    const float* B = P + (long)b * SEQ * PW + DM;   // K

    const uint32_t uA = (uint32_t)__cvta_generic_to_shared(Asb);
    const uint32_t uB = (uint32_t)__cvta_generic_to_shared(Bsb);
    const uint32_t uS = (uint32_t)__cvta_generic_to_shared(Ss);

    // A loader: 2 quads; rows (tid>>3)+{0,32}, col (tid&7)*4
    const int arow = tid >> 3;
    const int acol = (tid & 7) * 4;
    const bool aok0 = (m0 + arow) < SEQ;
    const bool aok1 = (m0 + arow + 32) < SEQ;
    const float* aptr = A + (long)(m0 + arow) * PW + acol;
    const uint32_t adst = uA + (uint32_t)(arow * 36 + acol) * 4;

    // B loader (NT): 4 quads; rows (tid>>3)+{0,32,64,96}
    bool bok[4];
#pragma unroll
    for (int j = 0; j < 4; j++) bok[j] = (n0 + arow + j * 32) < SEQ;
    const float* bptr = B + (long)(n0 + arow) * PW + acol;
    const uint32_t bdst = uB + (uint32_t)(arow * 36 + acol) * 4;

    float acc[2][4][4];
#pragma unroll
    for (int mt = 0; mt < 2; mt++)
#pragma unroll
        for (int nt = 0; nt < 4; nt++)
#pragma unroll
            for (int r = 0; r < 4; r++) acc[mt][nt][r] = 0.f;

    // S prefetch: 64 rows x 36 quads = 2304 quads, 8 chunks of 288
    auto s_chunk = [&](int ci) {
#pragma unroll
        for (int part = 0; part < 2; part++) {
            const int t = part * 256 + tid;
            if (part == 1 && tid >= 32) break;
            const int gq = ci * 288 + t;         // < 2304
            const int r = gq / 36;
            const int q = gq % 36;
            const int base = (w0 - r) & ~3;
            const int col = base + q * 4;
            const bool ok = ((m0 + r) < SEQ) && (col >= 0) && (col < 893);
            const float* src = S + (long)(b * SEQ + m0 + r) * ND2 + col;
            cpa16(uS + (uint32_t)(r * SROW + q * 4) * 4, src, ok);
        }
    };

    auto load_stage = [&](int buf, int k0, int ci) {
        const uint32_t ao = (uint32_t)buf * (ASZ * 4);
        const uint32_t bo = (uint32_t)buf * (BSZ * 4);
        cpa16(adst + ao, aptr + k0, aok0);
        cpa16(adst + ao + (uint32_t)(32 * 36) * 4, aptr + (long)32 * PW + k0, aok1);
#pragma unroll
        for (int j = 0; j < 4; j++)
            cpa16(bdst + bo + (uint32_t)(j * 32 * 36) * 4,
                  bptr + (long)(j * 32) * PW + k0, bok[j]);
        s_chunk(ci);
        cpa_commit();
    };

    const int nk = DM >> 5;   // 8
    load_stage(0, 0, 0);
    cpa_wait0();
    __syncthreads();

    int buf = 0;
    for (int kt = 0; kt < nk; kt++) {
        const bool more = (kt + 1 < nk);
        if (more) load_stage(buf ^ 1, (kt + 1) << 5, kt + 1);

        const float* Astage = Asb + buf * ASZ;
        const float* Bstage = Bsb + buf * BSZ;

        uint32_t af[2][2][4];
        uint32_t bf[2][4][2];
        auto ldfrag = [&](int h, int fb) {
            const int c = h * 8 + (lane & 3);
            const float* abase = Astage + (wm * 32 + (lane >> 2)) * 36 + c;
#pragma unroll
            for (int mt = 0; mt < 2; mt++) {
                af[fb][mt][0] = __float_as_uint(abase[(mt * 16    ) * 36    ]);
                af[fb][mt][1] = __float_as_uint(abase[(mt * 16 + 8) * 36    ]);
                af[fb][mt][2] = __float_as_uint(abase[(mt * 16    ) * 36 + 4]);
                af[fb][mt][3] = __float_as_uint(abase[(mt * 16 + 8) * 36 + 4]);
            }
#pragma unroll
            for (int nt = 0; nt < 4; nt++) {
                const int nB = wn * 32 + nt * 8 + (lane >> 2);
                bf[fb][nt][0] = __float_as_uint(Bstage[nB * 36 + c]);
                bf[fb][nt][1] = __float_as_uint(Bstage[nB * 36 + c + 4]);
            }
        };

        ldfrag(0, 0);
#pragma unroll
        for (int h = 0; h < 4; h++) {
            const int cu = h & 1;
            if (h < 3) ldfrag(h + 1, cu ^ 1);
#pragma unroll
            for (int mt = 0; mt < 2; mt++)
#pragma unroll
                for (int nt = 0; nt < 4; nt++)
                    mma8(acc[mt][nt], af[cu][mt], bf[cu][nt]);
        }

        if (more) {
            cpa_wait0();
            __syncthreads();
            buf ^= 1;
        }
    }

    // ---- fused combine epilogue (S from smem) ----
#pragma unroll
    for (int mt = 0; mt < 2; mt++) {
        const int ibase = m0 + wm * 32 + mt * 16 + (lane >> 2);
#pragma unroll
        for (int half = 0; half < 2; half++) {
            const int i = ibase + half * 8;
            if (i >= SEQ) continue;
            const int r = i - m0;
            const float* srow = Ss + r * SROW + ((w0 - r) & 3) - n0;
            const long obase = (long)b * SEQ * SEQ + (long)i * SEQ;
#pragma unroll
            for (int nt = 0; nt < 4; nt++) {
                const int cc = n0 + wn * 32 + nt * 8 + (lane & 3) * 2;
                if (cc >= SEQ) continue;   // cc even, so cc+1 <= 399
                const float v0 = (acc[mt][nt][half * 2 + 0] + srow[cc])     * 0.0625f;
                const float v1 = (acc[mt][nt][half * 2 + 1] + srow[cc + 1]) * 0.0625f;
                *(float2*)&out[obase + cc] = make_float2(v0, v1);
            }
        }
    }
}

extern "C" void kernel_launch(void* const* d_in, const int* in_sizes, int n_in,
                              void* d_out, int out_size)
{
    const float* x    = (const float*)d_in[0];  // (8,400,512)
    const int*   mask = (const int*)  d_in[1];  // (8,400)
    const float* w_q  = (const float*)d_in[2];  // (512,256)
    const float* w_q2 = (const float*)d_in[3];  // (512,256)
    const float* w_k  = (const float*)d_in[4];  // (512,256)
    const float* w_k2 = (const float*)d_in[5];  // (256,256)
    const float* rel  = (const float*)d_in[6];  // (1,400,400,256)
    float* out = (float*)d_out;

    float *Xt, *Wcat, *P, *RT, *S;
    cudaGetSymbolAddress((void**)&Xt,   g_Xt);
    cudaGetSymbolAddress((void**)&Wcat, g_Wcat);
    cudaGetSymbolAddress((void**)&P,    g_P);
    cudaGetSymbolAddress((void**)&RT,   g_RT);
    cudaGetSymbolAddress((void**)&S,    g_S);

    const int smemT = (2 * 64 * 36 + 2 * 32 * 136) * 4;             // 53248
    const int smemE = (2 * 64 * 36 + 2 * 128 * 36 + 64 * 148) * 4;  // 93184
    cudaFuncSetAttribute(mmaT<true>,
        cudaFuncAttributeMaxDynamicSharedMemorySize, smemT);
    cudaFuncSetAttribute(mmaT<false>,
        cudaFuncAttributeMaxDynamicSharedMemorySize, smemT);
    cudaFuncSetAttribute(mmaE,
        cudaFuncAttributeMaxDynamicSharedMemorySize, smemE);

    // 1) All setup in one launch (Xt, Wcat, RT, mask half of out)
    setup_all<<<SB4, 256>>>(x, w_q, w_k, w_q2, w_k2, rel, mask,
                            Xt, Wcat, RT, out, out_size);

    // 2) P = Xt @ Wcat  (3200x768x512), output tf32-rounded  (300 CTAs)
    mmaT<true><<<dim3(PW / 128, BS / 64), 256, smemT>>>(
        Xt, Wcat, P, SD, SD, PW, PW);

    // 3) S = P[:,512:768) @ RT  (3200x896x256), output fp32  (350 CTAs)
    mmaT<false><<<dim3(ND2 / 128, BS / 64), 256, smemT>>>(
        P + SD, RT, S, DM, PW, ND2, ND2);

    // 4) E = Q @ K^T fused with combine + smem S window (224 CTAs)
    mmaE<<<dim3(4, 7, BATCH), 256, smemE>>>(P, S, out);
}

// round 14
// speedup vs baseline: 1.9081x; 1.0825x over previous
#include <cuda_runtime.h>
#include <cstdint>

#define SEQ 400
#define BATCH 8
#define DM 256          // d_model
#define SD 512          // source_dim
#define PW 768          // packed projection width: [Q | K | Q2W]
#define ND2 896         // delta columns padded (799 real)
#define BS (BATCH*SEQ)          // 3200
#define BSS (BATCH*SEQ*SEQ)     // 1280000

// Scratch (device globals — no allocations allowed)
__device__ float g_Xt[BS*SD];        // tf32-rounded x              (3200x512)
__device__ float g_Wcat[SD*PW];      // [w_q | w_k | w_q2@w_k2^T]   (512x768) tf32
__device__ float g_P[BS*PW];         // Xt @ Wcat                   (3200x768) tf32
__device__ float g_RT[DM*ND2];       // R^T: [d][delta+399]         (256x896) tf32
__device__ float g_S[BS*ND2];        // band of P[:,512:768] @ RT   (3200x896) fp32

// ---------------------------------------------------------------------------
__device__ __forceinline__ float f2tf32(float f) {
    uint32_t u;
    asm("cvt.rna.tf32.f32 %0, %1;" : "=r"(u) : "f"(f));
    return __uint_as_float(u);
}

__device__ __forceinline__ void mma8(float c[4], const uint32_t a[4], const uint32_t b[2]) {
    asm volatile("mma.sync.aligned.m16n8k8.row.col.f32.tf32.tf32.f32 "
        "{%0,%1,%2,%3}, {%4,%5,%6,%7}, {%8,%9}, {%0,%1,%2,%3};"
        : "+f"(c[0]), "+f"(c[1]), "+f"(c[2]), "+f"(c[3])
        : "r"(a[0]), "r"(a[1]), "r"(a[2]), "r"(a[3]), "r"(b[0]), "r"(b[1]));
}

__device__ __forceinline__ void cpa16(uint32_t dst, const float* src, bool p) {
    asm volatile("cp.async.cg.shared.global [%0], [%1], 16, %2;"
                 :: "r"(dst), "l"(src), "r"(p ? 16 : 0));
}
__device__ __forceinline__ void cpa_commit() {
    asm volatile("cp.async.commit_group;");
}
__device__ __forceinline__ void cpa_wait0() {
    asm volatile("cp.async.wait_group 0;");
}

// ---------------------------------------------------------------------------
// Fused setup kernel — all sections independent, one launch, 256 threads:
//   S0: Xt = tf32(x)            (4 float4/thread)     blocks [0, 400)
//   S1: Wcat[:, 0:512)                                 blocks [400, 528)
//   S2: RT transposed gather                           blocks [528, 640)
//   S3: Wcat[:, 512:768) = tf32(w_q2 @ w_k2^T)         blocks [640, 672)
//   S4: out[BSS..2BSS) = mask   (2 float4/thread)      blocks [672, 1297)
// ---------------------------------------------------------------------------
#define SB0 400
#define SB1 (SB0 + 128)
#define SB2 (SB1 + 112)
#define SB3 (SB2 + 32)
#define SB4 (SB3 + 625)

__global__ __launch_bounds__(256)
void setup_all(const float* __restrict__ x,
               const float* __restrict__ wq, const float* __restrict__ wk,
               const float* __restrict__ wq2, const float* __restrict__ wk2,
               const float* __restrict__ rel, const int* __restrict__ mask,
               float* __restrict__ Xt, float* __restrict__ Wcat,
               float* __restrict__ RT, float* __restrict__ out, int out_size)
{
    __shared__ float sh[2176 * 2];
    const int blk = blockIdx.x;
    const int tid = threadIdx.x;

    if (blk < SB0) {
        // ---- S0: tf32-round x, 4 strided float4s per thread
#pragma unroll
        for (int j = 0; j < 4; j++) {
            const int idx = blk * 1024 + j * 256 + tid;
            float4 v = ((const float4*)x)[idx];
            v.x = f2tf32(v.x); v.y = f2tf32(v.y); v.z = f2tf32(v.z); v.w = f2tf32(v.w);
            ((float4*)Xt)[idx] = v;
        }
    } else if (blk < SB1) {
        const int idx = (blk - SB0) * 256 + tid;
        const int row = idx / (DM / 4);
        const int c4  = idx % (DM / 4);
        float4 q = ((const float4*)wq)[idx];
        float4 k = ((const float4*)wk)[idx];
        q.x = f2tf32(q.x); q.y = f2tf32(q.y); q.z = f2tf32(q.z); q.w = f2tf32(q.w);
        k.x = f2tf32(k.x); k.y = f2tf32(k.y); k.z = f2tf32(k.z); k.w = f2tf32(k.w);
        ((float4*)(Wcat + (long)row * PW))[c4] = q;
        ((float4*)(Wcat + (long)row * PW + DM))[c4] = k;
    } else if (blk < SB2) {
        float (*t)[65] = (float(*)[65])sh;
        const int blk2 = blk - SB1;
        const int m0 = (blk2 % 28) * 32;
        const int d0 = (blk2 / 28) * 64;
        const int dl = tid & 63, mb = tid >> 6;
#pragma unroll
        for (int it = 0; it < 8; it++) {
            const int ml = mb * 8 + it;
            const int m = m0 + ml;
            float v = 0.f;
            if (m <= 798) {
                const int delta = m - 399;
                const long off = (delta >= 0) ? (long)delta * DM
                                              : (long)(-delta) * SEQ * DM;
                v = f2tf32(rel[off + d0 + dl]);
            }
            t[ml][dl] = v;
        }
        __syncthreads();
        const int ml2 = tid & 31, db = tid >> 5;
#pragma unroll
        for (int it = 0; it < 8; it++) {
            const int dl2 = db + it * 8;
            RT[(long)(d0 + dl2) * ND2 + m0 + ml2] = t[ml2][dl2];
        }
    } else if (blk < SB3) {
        float (*As)[68] = (float(*)[68])sh;
        float (*Bs)[68] = (float(*)[68])(sh + 16 * 68);
        const int blk2 = blk - SB2;
        const int m0 = (blk2 >> 2) * 64, n0 = (blk2 & 3) * 64;
        const int tx = tid & 15, ty = tid >> 4;
        const int ar = tid >> 2, ak = (tid & 3) * 4;
        float acc[4][4] = {};
        for (int k0 = 0; k0 < DM; k0 += 16) {
            float4 v = *(const float4*)(wq2 + (long)(m0 + ar) * DM + k0 + ak);
            As[ak][ar] = v.x; As[ak+1][ar] = v.y; As[ak+2][ar] = v.z; As[ak+3][ar] = v.w;
            float4 w = *(const float4*)(wk2 + (long)(n0 + ar) * DM + k0 + ak);
            Bs[ak][ar] = w.x; Bs[ak+1][ar] = w.y; Bs[ak+2][ar] = w.z; Bs[ak+3][ar] = w.w;
            __syncthreads();
#pragma unroll
            for (int kk = 0; kk < 16; kk++) {
                const float4 a = *(const float4*)&As[kk][ty * 4];
                const float4 b = *(const float4*)&Bs[kk][tx * 4];
                acc[0][0]+=a.x*b.x; acc[0][1]+=a.x*b.y; acc[0][2]+=a.x*b.z; acc[0][3]+=a.x*b.w;
                acc[1][0]+=a.y*b.x; acc[1][1]+=a.y*b.y; acc[1][2]+=a.y*b.z; acc[1][3]+=a.y*b.w;
                acc[2][0]+=a.z*b.x; acc[2][1]+=a.z*b.y; acc[2][2]+=a.z*b.z; acc[2][3]+=a.z*b.w;
                acc[3][0]+=a.w*b.x; acc[3][1]+=a.w*b.y; acc[3][2]+=a.w*b.z; acc[3][3]+=a.w*b.w;
            }
            __syncthreads();
        }
#pragma unroll
        for (int r = 0; r < 4; r++)
#pragma unroll
            for (int c = 0; c < 4; c++)
                Wcat[(long)(m0 + ty*4 + r) * PW + SD + n0 + tx*4 + c] = f2tf32(acc[r][c]);
    } else if (blk < SB4) {
        // ---- S4: mask outer product, 2 strided float4s per thread
        if (out_size < 2 * BSS) return;
        const int blk2 = blk - SB3;
#pragma unroll
        for (int part = 0; part < 2; part++) {
            const long idx = ((long)blk2 * 512 + part * 256 + tid) * 4;
            if (idx >= BSS) continue;
            const int j = (int)(idx % SEQ);      // SEQ%4==0: no row crossing
            const int bi = (int)(idx / SEQ);
            const int i = bi % SEQ, b = bi / SEQ;
            const float mi = (float)mask[b * SEQ + i];
            float4 o;
            o.x = mi * mask[b * SEQ + j];
            o.y = mi * mask[b * SEQ + j + 1];
            o.z = mi * mask[b * SEQ + j + 2];
            o.w = mi * mask[b * SEQ + j + 3];
            *(float4*)&out[BSS + idx] = o;
        }
    }
}

// ---------------------------------------------------------------------------
// tf32 NN GEMM, 64x128 tile, BK=32, 256 threads (8 warps 2x4, warp 32x32).
// Two-stage cp.async, conflict-free padded smem (A pad 36, B pad 136).
//
// BAND=false (P GEMM): C = A[M,K]@B[K,N], grid (N/128, M/64); M%64==0.
// BAND=true  (S GEMM): per-batch diagonal band. grid (4, 7, BATCH).
//   b=blockIdx.z selects batch (A += b*400*lda, C += b*400*ldc);
//   row block i0=blockIdx.y*64 (rows >= 400 predicated off);
//   column base nbase = max(0, 336-i0); n0 = nbase + blockIdx.x*128.
//   Covers all consumed m = j-i+399 (proof in header comment of launch).
// OTF: tf32-round C on store.
// ---------------------------------------------------------------------------
template <bool OTF, bool BAND>
__global__ __launch_bounds__(256, 2)
void mmaT(const float* __restrict__ A, const float* __restrict__ B,
          float* __restrict__ C, int K, int lda, int ldb, int ldc)
{
    constexpr int ASZ = 64 * 36;
    constexpr int BSZ = 32 * 136;
    extern __shared__ float sh[];
    float* Asb = sh;
    float* Bsb = sh + 2 * ASZ;

    const int tid  = threadIdx.x;
    const int lane = tid & 31;
    const int wid  = tid >> 5;
    const int wm   = wid >> 2;
    const int wn   = wid & 3;

    int m0, n0;
    if (BAND) {
        const int b = blockIdx.z;
        A += (long)b * SEQ * lda;
        C += (long)b * SEQ * ldc;
        m0 = blockIdx.y * 64;
        const int nbase = (336 - m0) > 0 ? (336 - m0) : 0;
        n0 = nbase + blockIdx.x * 128;
    } else {
        m0 = blockIdx.y * 64;
        n0 = blockIdx.x * 128;
    }

    const uint32_t uA = (uint32_t)__cvta_generic_to_shared(Asb);
    const uint32_t uB = (uint32_t)__cvta_generic_to_shared(Bsb);

    // A loader: 2 quads; rows (tid>>3)+{0,32}, col (tid&7)*4
    const int arow = tid >> 3;
    const int acol = (tid & 7) * 4;
    const bool aok0 = !BAND || (m0 + arow)      < SEQ;
    const bool aok1 = !BAND || (m0 + arow + 32) < SEQ;
    const float* aptr = A + (long)(m0 + (aok0 ? arow : 0)) * lda + acol;
    const float* aptr1 = A + (long)(m0 + (aok1 ? arow + 32 : 0)) * lda + acol;
    const uint32_t adst = uA + (uint32_t)(arow * 36 + acol) * 4;

    // B loader: 4 quads; rows (tid>>5)+{0,8,16,24}, col (tid&31)*4
    const int brow = tid >> 5;
    const int bcol = (tid & 31) * 4;
    const float* bptr = B + (long)brow * ldb + n0 + bcol;
    const uint32_t bdst = uB + (uint32_t)(brow * 136 + bcol) * 4;

    float acc[2][4][4];
#pragma unroll
    for (int mt = 0; mt < 2; mt++)
#pragma unroll
        for (int nt = 0; nt < 4; nt++)
#pragma unroll
            for (int r = 0; r < 4; r++) acc[mt][nt][r] = 0.f;

    auto load_stage = [&](int buf, int k0) {
        const uint32_t ao = (uint32_t)buf * (ASZ * 4);
        const uint32_t bo = (uint32_t)buf * (BSZ * 4);
        cpa16(adst + ao, aptr + k0, aok0);
        cpa16(adst + ao + (uint32_t)(32 * 36) * 4, aptr1 + k0, aok1);
#pragma unroll
        for (int j = 0; j < 4; j++)
            cpa16(bdst + bo + (uint32_t)(j * 8 * 136) * 4,
                  bptr + (long)(k0 + j * 8) * ldb, true);
        cpa_commit();
    };

    load_stage(0, 0);
    cpa_wait0();
    __syncthreads();

    const int nk = K >> 5;
    int buf = 0;
    for (int kt = 0; kt < nk; kt++) {
        const bool more = (kt + 1 < nk);
        if (more) load_stage(buf ^ 1, (kt + 1) << 5);

        const float* Astage = Asb + buf * ASZ;
        const float* Bstage = Bsb + buf * BSZ;
#pragma unroll
        for (int h = 0; h < 4; h++) {
            const int c = h * 8 + (lane & 3);
            uint32_t af[2][4];
            uint32_t bf[4][2];
            const float* abase = Astage + (wm * 32 + (lane >> 2)) * 36 + c;
#pragma unroll
            for (int mt = 0; mt < 2; mt++) {
                af[mt][0] = __float_as_uint(abase[(mt * 16    ) * 36    ]);
                af[mt][1] = __float_as_uint(abase[(mt * 16 + 8) * 36    ]);
                af[mt][2] = __float_as_uint(abase[(mt * 16    ) * 36 + 4]);
                af[mt][3] = __float_as_uint(abase[(mt * 16 + 8) * 36 + 4]);
            }
#pragma unroll
            for (int nt = 0; nt < 4; nt++) {
                const int nB = wn * 32 + nt * 8 + (lane >> 2);
                bf[nt][0] = __float_as_uint(Bstage[(c    ) * 136 + nB]);
                bf[nt][1] = __float_as_uint(Bstage[(c + 4) * 136 + nB]);
            }
#pragma unroll
            for (int mt = 0; mt < 2; mt++)
#pragma unroll
                for (int nt = 0; nt < 4; nt++)
                    mma8(acc[mt][nt], af[mt], bf[nt]);
        }

        if (more) {
            cpa_wait0();
            __syncthreads();
            buf ^= 1;
        }
    }

#pragma unroll
    for (int mt = 0; mt < 2; mt++) {
        const int r0 = m0 + wm * 32 + mt * 16 + (lane >> 2);
        const int r1 = r0 + 8;
        const bool ok0 = !BAND || r0 < SEQ;
        const bool ok1 = !BAND || r1 < SEQ;
#pragma unroll
        for (int nt = 0; nt < 4; nt++) {
            const int cc = n0 + wn * 32 + nt * 8 + (lane & 3) * 2;
            float v0 = acc[mt][nt][0], v1 = acc[mt][nt][1];
            float v2 = acc[mt][nt][2], v3 = acc[mt][nt][3];
            if (OTF) { v0 = f2tf32(v0); v1 = f2tf32(v1); v2 = f2tf32(v2); v3 = f2tf32(v3); }
            if (ok0) *(float2*)&C[(long)r0 * ldc + cc] = make_float2(v0, v1);
            if (ok1) *(float2*)&C[(long)r1 * ldc + cc] = make_float2(v2, v3);
        }
    }
}

// ---------------------------------------------------------------------------
// E = Q @ K^T fused with combine. 64x128 tile, BK=32, 8 warps 2x4 (warp
// 32x32). S diagonal window prefetched into smem alongside mainloop stages.
// ---------------------------------------------------------------------------
__global__ __launch_bounds__(256, 2)
void mmaE(const float* __restrict__ P, const float* __restrict__ S,
          float* __restrict__ out)
{
    constexpr int ASZ = 64 * 36;
    constexpr int BSZ = 128 * 36;
    constexpr int SROW = 148;           // 144 data + 4 pad
    extern __shared__ float sh[];
    float* Asb = sh;                    // 2 stages
    float* Bsb = sh + 2 * ASZ;          // 2 stages
    float* Ss  = sh + 2 * ASZ + 2 * BSZ;// 64 x 148

    const int tid  = threadIdx.x;
    const int lane = tid & 31;
    const int wid  = tid >> 5;
    const int wm   = wid >> 2;
    const int wn   = wid & 3;
    const int m0   = blockIdx.y * 64;
    const int n0   = blockIdx.x * 128;
    const int b    = blockIdx.z;
    const int w0   = n0 - m0 + 399;

    const float* A = P + (long)b * SEQ * PW;        // Q
    const float* B = P + (long)b * SEQ * PW + DM;   // K

    const uint32_t uA = (uint32_t)__cvta_generic_to_shared(Asb);
    const uint32_t uB = (uint32_t)__cvta_generic_to_shared(Bsb);
    const uint32_t uS = (uint32_t)__cvta_generic_to_shared(Ss);

    // A loader: 2 quads; rows (tid>>3)+{0,32}, col (tid&7)*4
    const int arow = tid >> 3;
    const int acol = (tid & 7) * 4;
    const bool aok0 = (m0 + arow) < SEQ;
    const bool aok1 = (m0 + arow + 32) < SEQ;
    const float* aptr = A + (long)(m0 + arow) * PW + acol;
    const uint32_t adst = uA + (uint32_t)(arow * 36 + acol) * 4;

    // B loader (NT): 4 quads; rows (tid>>3)+{0,32,64,96}
    bool bok[4];
#pragma unroll
    for (int j = 0; j < 4; j++) bok[j] = (n0 + arow + j * 32) < SEQ;
    const float* bptr = B + (long)(n0 + arow) * PW + acol;
    const uint32_t bdst = uB + (uint32_t)(arow * 36 + acol) * 4;

    float acc[2][4][4];
#pragma unroll
    for (int mt = 0; mt < 2; mt++)
#pragma unroll
        for (int nt = 0; nt < 4; nt++)
#pragma unroll
            for (int r = 0; r < 4; r++) acc[mt][nt][r] = 0.f;

    // S prefetch: 64 rows x 36 quads = 2304 quads, 8 chunks of 288
    auto s_chunk = [&](int ci) {
#pragma unroll
        for (int part = 0; part < 2; part++) {
            const int t = part * 256 + tid;
            if (part == 1 && tid >= 32) break;
            const int gq = ci * 288 + t;         // < 2304
            const int r = gq / 36;
            const int q = gq % 36;
            const int base = (w0 - r) & ~3;
            const int col = base + q * 4;
            const bool ok = ((m0 + r) < SEQ) && (col >= 0) && (col < 893);
            const float* src = S + (long)(b * SEQ + m0 + r) * ND2 + col;
            cpa16(uS + (uint32_t)(r * SROW + q * 4) * 4, src, ok);
        }
    };

    auto load_stage = [&](int buf, int k0, int ci) {
        const uint32_t ao = (uint32_t)buf * (ASZ * 4);
        const uint32_t bo = (uint32_t)buf * (BSZ * 4);
        cpa16(adst + ao, aptr + k0, aok0);
        cpa16(adst + ao + (uint32_t)(32 * 36) * 4, aptr + (long)32 * PW + k0, aok1);
#pragma unroll
        for (int j = 0; j < 4; j++)
            cpa16(bdst + bo + (uint32_t)(j * 32 * 36) * 4,
                  bptr + (long)(j * 32) * PW + k0, bok[j]);
        s_chunk(ci);
        cpa_commit();
    };

    const int nk = DM >> 5;   // 8
    load_stage(0, 0, 0);
    cpa_wait0();
    __syncthreads();

    int buf = 0;
    for (int kt = 0; kt < nk; kt++) {
        const bool more = (kt + 1 < nk);
        if (more) load_stage(buf ^ 1, (kt + 1) << 5, kt + 1);

        const float* Astage = Asb + buf * ASZ;
        const float* Bstage = Bsb + buf * BSZ;
#pragma unroll
        for (int h = 0; h < 4; h++) {
            const int c = h * 8 + (lane & 3);
            uint32_t af[2][4];
            uint32_t bf[4][2];
            const float* abase = Astage + (wm * 32 + (lane >> 2)) * 36 + c;
#pragma unroll
            for (int mt = 0; mt < 2; mt++) {
                af[mt][0] = __float_as_uint(abase[(mt * 16    ) * 36    ]);
                af[mt][1] = __float_as_uint(abase[(mt * 16 + 8) * 36    ]);
                af[mt][2] = __float_as_uint(abase[(mt * 16    ) * 36 + 4]);
                af[mt][3] = __float_as_uint(abase[(mt * 16 + 8) * 36 + 4]);
            }
#pragma unroll
            for (int nt = 0; nt < 4; nt++) {
                const int nB = wn * 32 + nt * 8 + (lane >> 2);
                bf[nt][0] = __float_as_uint(Bstage[nB * 36 + c]);
                bf[nt][1] = __float_as_uint(Bstage[nB * 36 + c + 4]);
            }
#pragma unroll
            for (int mt = 0; mt < 2; mt++)
#pragma unroll
                for (int nt = 0; nt < 4; nt++)
                    mma8(acc[mt][nt], af[mt], bf[nt]);
        }

        if (more) {
            cpa_wait0();
            __syncthreads();
            buf ^= 1;
        }
    }

    // ---- fused combine epilogue (S from smem) ----
#pragma unroll
    for (int mt = 0; mt < 2; mt++) {
        const int ibase = m0 + wm * 32 + mt * 16 + (lane >> 2);
#pragma unroll
        for (int half = 0; half < 2; half++) {
            const int i = ibase + half * 8;
            if (i >= SEQ) continue;
            const int r = i - m0;
            const float* srow = Ss + r * SROW + ((w0 - r) & 3) - n0;
            const long obase = (long)b * SEQ * SEQ + (long)i * SEQ;
#pragma unroll
            for (int nt = 0; nt < 4; nt++) {
                const int cc = n0 + wn * 32 + nt * 8 + (lane & 3) * 2;
                if (cc >= SEQ) continue;   // cc even, so cc+1 <= 399
                const float v0 = (acc[mt][nt][half * 2 + 0] + srow[cc])     * 0.0625f;
                const float v1 = (acc[mt][nt][half * 2 + 1] + srow[cc + 1]) * 0.0625f;
                *(float2*)&out[obase + cc] = make_float2(v0, v1);
            }
        }
    }
}

extern "C" void kernel_launch(void* const* d_in, const int* in_sizes, int n_in,
                              void* d_out, int out_size)
{
    const float* x    = (const float*)d_in[0];  // (8,400,512)
    const int*   mask = (const int*)  d_in[1];  // (8,400)
    const float* w_q  = (const float*)d_in[2];  // (512,256)
    const float* w_q2 = (const float*)d_in[3];  // (512,256)
    const float* w_k  = (const float*)d_in[4];  // (512,256)
    const float* w_k2 = (const float*)d_in[5];  // (256,256)
    const float* rel  = (const float*)d_in[6];  // (1,400,400,256)
    float* out = (float*)d_out;

    float *Xt, *Wcat, *P, *RT, *S;
    cudaGetSymbolAddress((void**)&Xt,   g_Xt);
    cudaGetSymbolAddress((void**)&Wcat, g_Wcat);
    cudaGetSymbolAddress((void**)&P,    g_P);
    cudaGetSymbolAddress((void**)&RT,   g_RT);
    cudaGetSymbolAddress((void**)&S,    g_S);

    const int smemT = (2 * 64 * 36 + 2 * 32 * 136) * 4;             // 53248
    const int smemE = (2 * 64 * 36 + 2 * 128 * 36 + 64 * 148) * 4;  // 93184
    cudaFuncSetAttribute(mmaT<true, false>,
        cudaFuncAttributeMaxDynamicSharedMemorySize, smemT);
    cudaFuncSetAttribute(mmaT<false, true>,
        cudaFuncAttributeMaxDynamicSharedMemorySize, smemT);
    cudaFuncSetAttribute(mmaE,
        cudaFuncAttributeMaxDynamicSharedMemorySize, smemE);

    // 1) All setup in one launch (Xt, Wcat, RT, mask half of out)
    setup_all<<<SB4, 256>>>(x, w_q, w_k, w_q2, w_k2, rel, mask,
                            Xt, Wcat, RT, out, out_size);

    // 2) P = Xt @ Wcat  (3200x768x512), output tf32-rounded  (300 CTAs)
    mmaT<true, false><<<dim3(PW / 128, BS / 64), 256, smemT>>>(
        Xt, Wcat, P, SD, SD, PW, PW);

    // 3) S band = P[:,512:768) @ RT, only the consumed diagonal band.
    //    Per batch b, row block i0: needed m in [max(0,336-i0), 798-i0]
    //    (width <= 463); 4 tiles of 128 from nbase = max(0,336-i0) cover it.
    //    grid (4, 7, 8) = 224 CTAs vs 350 full.
    mmaT<false, true><<<dim3(4, 7, BATCH), 256, smemT>>>(
        P + SD, RT, S, DM, PW, ND2, ND2);

    // 4) E = Q @ K^T fused with combine + smem S window (224 CTAs)
    mmaE<<<dim3(4, 7, BATCH), 256, smemE>>>(P, S, out);
}

// round 15
// speedup vs baseline: 2.0652x; 1.0823x over previous
#include <cuda_runtime.h>
#include <cstdint>

#define SEQ 400
#define BATCH 8
#define DM 256          // d_model
#define SD 512          // source_dim
#define PW 768          // packed projection width: [Q | K | Q2W]
#define ND2 896         // delta columns padded (799 real)
#define BS (BATCH*SEQ)          // 3200
#define BSS (BATCH*SEQ*SEQ)     // 1280000

// Scratch (device globals — no allocations allowed)
__device__ float g_Wcat[SD*PW];      // [w_q | w_k | w_q2@w_k2^T]   (512x768) tf32
__device__ float g_P[BS*PW];         // x @ Wcat                    (3200x768) tf32
__device__ float g_RT[DM*ND2];       // R^T: [d][delta+399]         (256x896) tf32
__device__ float g_S[BS*ND2];        // band of P[:,512:768] @ RT   (3200x896) fp32

// ---------------------------------------------------------------------------
__device__ __forceinline__ float f2tf32(float f) {
    uint32_t u;
    asm("cvt.rna.tf32.f32 %0, %1;" : "=r"(u) : "f"(f));
    return __uint_as_float(u);
}

__device__ __forceinline__ void mma8(float c[4], const uint32_t a[4], const uint32_t b[2]) {
    asm volatile("mma.sync.aligned.m16n8k8.row.col.f32.tf32.tf32.f32 "
        "{%0,%1,%2,%3}, {%4,%5,%6,%7}, {%8,%9}, {%0,%1,%2,%3};"
        : "+f"(c[0]), "+f"(c[1]), "+f"(c[2]), "+f"(c[3])
        : "r"(a[0]), "r"(a[1]), "r"(a[2]), "r"(a[3]), "r"(b[0]), "r"(b[1]));
}

__device__ __forceinline__ void cpa16(uint32_t dst, const float* src, bool p) {
    asm volatile("cp.async.cg.shared.global [%0], [%1], 16, %2;"
                 :: "r"(dst), "l"(src), "r"(p ? 16 : 0));
}
__device__ __forceinline__ void cpa_commit() {
    asm volatile("cp.async.commit_group;");
}
__device__ __forceinline__ void cpa_wait0() {
    asm volatile("cp.async.wait_group 0;");
}

// ---------------------------------------------------------------------------
// Fused setup kernel — all sections independent, one launch, 256 threads:
//   S1: Wcat[:, 0:512) = tf32([w_q | w_k])            blocks [0, 128)
//   S2: RT transposed gather (tf32)                    blocks [128, 240)
//   S3: Wcat[:, 512:768) = tf32(w_q2 @ w_k2^T)         blocks [240, 272)
//   S4: out[BSS..2BSS) = mask outer product            blocks [272, 897)
// (x is no longer pre-rounded: the P GEMM cvt's A-fragments in-register.)
// ---------------------------------------------------------------------------
#define SB1 128
#define SB2 (SB1 + 112)
#define SB3 (SB2 + 32)
#define SB4 (SB3 + 625)

__global__ __launch_bounds__(256)
void setup_all(const float* __restrict__ wq, const float* __restrict__ wk,
               const float* __restrict__ wq2, const float* __restrict__ wk2,
               const float* __restrict__ rel, const int* __restrict__ mask,
               float* __restrict__ Wcat, float* __restrict__ RT,
               float* __restrict__ out, int out_size)
{
    __shared__ float sh[2176 * 2];
    const int blk = blockIdx.x;
    const int tid = threadIdx.x;

    if (blk < SB1) {
        const int idx = blk * 256 + tid;
        const int row = idx / (DM / 4);
        const int c4  = idx % (DM / 4);
        float4 q = ((const float4*)wq)[idx];
        float4 k = ((const float4*)wk)[idx];
        q.x = f2tf32(q.x); q.y = f2tf32(q.y); q.z = f2tf32(q.z); q.w = f2tf32(q.w);
        k.x = f2tf32(k.x); k.y = f2tf32(k.y); k.z = f2tf32(k.z); k.w = f2tf32(k.w);
        ((float4*)(Wcat + (long)row * PW))[c4] = q;
        ((float4*)(Wcat + (long)row * PW + DM))[c4] = k;
    } else if (blk < SB2) {
        float (*t)[65] = (float(*)[65])sh;
        const int blk2 = blk - SB1;
        const int m0 = (blk2 % 28) * 32;
        const int d0 = (blk2 / 28) * 64;
        const int dl = tid & 63, mb = tid >> 6;
#pragma unroll
        for (int it = 0; it < 8; it++) {
            const int ml = mb * 8 + it;
            const int m = m0 + ml;
            float v = 0.f;
            if (m <= 798) {
                const int delta = m - 399;
                const long off = (delta >= 0) ? (long)delta * DM
                                              : (long)(-delta) * SEQ * DM;
                v = f2tf32(rel[off + d0 + dl]);
            }
            t[ml][dl] = v;
        }
        __syncthreads();
        const int ml2 = tid & 31, db = tid >> 5;
#pragma unroll
        for (int it = 0; it < 8; it++) {
            const int dl2 = db + it * 8;
            RT[(long)(d0 + dl2) * ND2 + m0 + ml2] = t[ml2][dl2];
        }
    } else if (blk < SB3) {
        float (*As)[68] = (float(*)[68])sh;
        float (*Bs)[68] = (float(*)[68])(sh + 16 * 68);
        const int blk2 = blk - SB2;
        const int m0 = (blk2 >> 2) * 64, n0 = (blk2 & 3) * 64;
        const int tx = tid & 15, ty = tid >> 4;
        const int ar = tid >> 2, ak = (tid & 3) * 4;
        float acc[4][4] = {};
        for (int k0 = 0; k0 < DM; k0 += 16) {
            float4 v = *(const float4*)(wq2 + (long)(m0 + ar) * DM + k0 + ak);
            As[ak][ar] = v.x; As[ak+1][ar] = v.y; As[ak+2][ar] = v.z; As[ak+3][ar] = v.w;
            float4 w = *(const float4*)(wk2 + (long)(n0 + ar) * DM + k0 + ak);
            Bs[ak][ar] = w.x; Bs[ak+1][ar] = w.y; Bs[ak+2][ar] = w.z; Bs[ak+3][ar] = w.w;
            __syncthreads();
#pragma unroll
            for (int kk = 0; kk < 16; kk++) {
                const float4 a = *(const float4*)&As[kk][ty * 4];
                const float4 b = *(const float4*)&Bs[kk][tx * 4];
                acc[0][0]+=a.x*b.x; acc[0][1]+=a.x*b.y; acc[0][2]+=a.x*b.z; acc[0][3]+=a.x*b.w;
                acc[1][0]+=a.y*b.x; acc[1][1]+=a.y*b.y; acc[1][2]+=a.y*b.z; acc[1][3]+=a.y*b.w;
                acc[2][0]+=a.z*b.x; acc[2][1]+=a.z*b.y; acc[2][2]+=a.z*b.z; acc[2][3]+=a.z*b.w;
                acc[3][0]+=a.w*b.x; acc[3][1]+=a.w*b.y; acc[3][2]+=a.w*b.z; acc[3][3]+=a.w*b.w;
            }
            __syncthreads();
        }
#pragma unroll
        for (int r = 0; r < 4; r++)
#pragma unroll
            for (int c = 0; c < 4; c++)
                Wcat[(long)(m0 + ty*4 + r) * PW + SD + n0 + tx*4 + c] = f2tf32(acc[r][c]);
    } else if (blk < SB4) {
        // ---- S4: mask outer product, 2 strided float4s per thread
        if (out_size < 2 * BSS) return;
        const int blk2 = blk - SB3;
#pragma unroll
        for (int part = 0; part < 2; part++) {
            const long idx = ((long)blk2 * 512 + part * 256 + tid) * 4;
            if (idx >= BSS) continue;
            const int j = (int)(idx % SEQ);      // SEQ%4==0: no row crossing
            const int bi = (int)(idx / SEQ);
            const int i = bi % SEQ, b = bi / SEQ;
            const float mi = (float)mask[b * SEQ + i];
            float4 o;
            o.x = mi * mask[b * SEQ + j];
            o.y = mi * mask[b * SEQ + j + 1];
            o.z = mi * mask[b * SEQ + j + 2];
            o.w = mi * mask[b * SEQ + j + 3];
            *(float4*)&out[BSS + idx] = o;
        }
    }
}

// ---------------------------------------------------------------------------
// tf32 NN GEMM, 64xNT tile (NT = 128 or 96), BK=32, 256 threads (8 warps
// 2x4, warp tile 32 x NT/4). Two-stage cp.async; conflict-free padded smem
// (A pad 36; B pad 136 for NT=128, 104 for NT=96 — both verified all-bank).
//
// BAND=false (P): C = A[M,K]@B[K,N], grid (N/NT, M/64); M%64==0.
// BAND=true  (S): per-batch diagonal band, grid (5, 7, BATCH);
//   n0 = max(0,336-m0) + bx*NT; rows >= 400 predicated.
// CVT: apply cvt.rna.tf32 to A-fragments (A is raw fp32: used by P on x).
// OTF: tf32-round C on store.
// ---------------------------------------------------------------------------
template <bool OTF, bool BAND, bool CVT, int NT>
__global__ __launch_bounds__(256, 2)
void mmaT(const float* __restrict__ A, const float* __restrict__ B,
          float* __restrict__ C, int K, int lda, int ldb, int ldc)
{
    constexpr int BC  = (NT == 128) ? 136 : 104;
    constexpr int NTC = NT / 32;          // nt count (4 or 3)
    constexpr int ASZ = 64 * 36;
    constexpr int BSZ = 32 * BC;
    extern __shared__ float sh[];
    float* Asb = sh;
    float* Bsb = sh + 2 * ASZ;

    const int tid  = threadIdx.x;
    const int lane = tid & 31;
    const int wid  = tid >> 5;
    const int wm   = wid >> 2;            // 0..1 -> 32-row half
    const int wn   = wid & 3;             // 0..3 -> NT/4-col quarter

    int m0, n0;
    if (BAND) {
        const int b = blockIdx.z;
        A += (long)b * SEQ * lda;
        C += (long)b * SEQ * ldc;
        m0 = blockIdx.y * 64;
        const int nbase = (336 - m0) > 0 ? (336 - m0) : 0;
        n0 = nbase + blockIdx.x * NT;
    } else {
        m0 = blockIdx.y * 64;
        n0 = blockIdx.x * NT;
    }

    const uint32_t uA = (uint32_t)__cvta_generic_to_shared(Asb);
    const uint32_t uB = (uint32_t)__cvta_generic_to_shared(Bsb);

    // A loader: 2 quads; rows (tid>>3)+{0,32}, col (tid&7)*4
    const int arow = tid >> 3;
    const int acol = (tid & 7) * 4;
    const bool aok0 = !BAND || (m0 + arow)      < SEQ;
    const bool aok1 = !BAND || (m0 + arow + 32) < SEQ;
    const float* aptr  = A + (long)(m0 + (aok0 ? arow : 0)) * lda + acol;
    const float* aptr1 = A + (long)(m0 + (aok1 ? arow + 32 : 0)) * lda + acol;
    const uint32_t adst = uA + (uint32_t)(arow * 36 + acol) * 4;

    float acc[2][NTC][4];
#pragma unroll
    for (int mt = 0; mt < 2; mt++)
#pragma unroll
        for (int nt = 0; nt < NTC; nt++)
#pragma unroll
            for (int r = 0; r < 4; r++) acc[mt][nt][r] = 0.f;

    auto load_stage = [&](int buf, int k0) {
        const uint32_t ao = (uint32_t)buf * (ASZ * 4);
        const uint32_t bo = (uint32_t)buf * (BSZ * 4);
        cpa16(adst + ao, aptr + k0, aok0);
        cpa16(adst + ao + (uint32_t)(32 * 36) * 4, aptr1 + k0, aok1);
        if (NT == 128) {
            const int brow = tid >> 5;          // 0..7 (+{0,8,16,24})
            const int bcol = (tid & 31) * 4;
#pragma unroll
            for (int j = 0; j < 4; j++)
                cpa16(uB + bo + (uint32_t)((brow + j * 8) * BC + bcol) * 4,
                      B + (long)(k0 + brow + j * 8) * ldb + n0 + bcol, true);
        } else {
            // NT=96: 32 rows x 24 quads = 768 quads, 3 per thread
#pragma unroll
            for (int j = 0; j < 3; j++) {
                const int q = tid + j * 256;
                const int r = q / 24;
                const int c = (q % 24) * 4;
                cpa16(uB + bo + (uint32_t)(r * BC + c) * 4,
                      B + (long)(k0 + r) * ldb + n0 + c, true);
            }
        }
        cpa_commit();
    };

    load_stage(0, 0);
    cpa_wait0();
    __syncthreads();

    const int nk = K >> 5;
    int buf = 0;
    for (int kt = 0; kt < nk; kt++) {
        const bool more = (kt + 1 < nk);
        if (more) load_stage(buf ^ 1, (kt + 1) << 5);

        const float* Astage = Asb + buf * ASZ;
        const float* Bstage = Bsb + buf * BSZ;
#pragma unroll
        for (int h = 0; h < 4; h++) {
            const int c = h * 8 + (lane & 3);
            uint32_t af[2][4];
            uint32_t bf[NTC][2];
            const float* abase = Astage + (wm * 32 + (lane >> 2)) * 36 + c;
#pragma unroll
            for (int mt = 0; mt < 2; mt++) {
                float a0 = abase[(mt * 16    ) * 36    ];
                float a1 = abase[(mt * 16 + 8) * 36    ];
                float a2 = abase[(mt * 16    ) * 36 + 4];
                float a3 = abase[(mt * 16 + 8) * 36 + 4];
                if (CVT) { a0 = f2tf32(a0); a1 = f2tf32(a1); a2 = f2tf32(a2); a3 = f2tf32(a3); }
                af[mt][0] = __float_as_uint(a0);
                af[mt][1] = __float_as_uint(a1);
                af[mt][2] = __float_as_uint(a2);
                af[mt][3] = __float_as_uint(a3);
            }
#pragma unroll
            for (int nt = 0; nt < NTC; nt++) {
                const int nB = wn * (NT / 4) + nt * 8 + (lane >> 2);
                bf[nt][0] = __float_as_uint(Bstage[(c    ) * BC + nB]);
                bf[nt][1] = __float_as_uint(Bstage[(c + 4) * BC + nB]);
            }
#pragma unroll
            for (int mt = 0; mt < 2; mt++)
#pragma unroll
                for (int nt = 0; nt < NTC; nt++)
                    mma8(acc[mt][nt], af[mt], bf[nt]);
        }

        if (more) {
            cpa_wait0();
            __syncthreads();
            buf ^= 1;
        }
    }

#pragma unroll
    for (int mt = 0; mt < 2; mt++) {
        const int r0 = m0 + wm * 32 + mt * 16 + (lane >> 2);
        const int r1 = r0 + 8;
        const bool ok0 = !BAND || r0 < SEQ;
        const bool ok1 = !BAND || r1 < SEQ;
#pragma unroll
        for (int nt = 0; nt < NTC; nt++) {
            const int cc = n0 + wn * (NT / 4) + nt * 8 + (lane & 3) * 2;
            float v0 = acc[mt][nt][0], v1 = acc[mt][nt][1];
            float v2 = acc[mt][nt][2], v3 = acc[mt][nt][3];
            if (OTF) { v0 = f2tf32(v0); v1 = f2tf32(v1); v2 = f2tf32(v2); v3 = f2tf32(v3); }
            if (ok0) *(float2*)&C[(long)r0 * ldc + cc] = make_float2(v0, v1);
            if (ok1) *(float2*)&C[(long)r1 * ldc + cc] = make_float2(v2, v3);
        }
    }
}

// ---------------------------------------------------------------------------
// E = Q @ K^T fused with combine. 64x96 tile (grid 5x7x8 = 280 CTAs ~ 296
// 2-res slots: ~94% balance), BK=32, 8 warps 2x4 (warp 32x24, nt=3).
// S diagonal window (64 x 104) prefetched into smem with mainloop stages.
// ---------------------------------------------------------------------------
__global__ __launch_bounds__(256, 2)
void mmaE(const float* __restrict__ P, const float* __restrict__ S,
          float* __restrict__ out)
{
    constexpr int ASZ = 64 * 36;
    constexpr int BSZ = 96 * 36;
    constexpr int SROW = 104;           // 100 data + 4 pad
    extern __shared__ float sh[];
    float* Asb = sh;                    // 2 stages
    float* Bsb = sh + 2 * ASZ;          // 2 stages
    float* Ss  = sh + 2 * ASZ + 2 * BSZ;// 64 x 104

    const int tid  = threadIdx.x;
    const int lane = tid & 31;
    const int wid  = tid >> 5;
    const int wm   = wid >> 2;          // 0..1 -> 32-row half
    const int wn   = wid & 3;           // 0..3 -> 24-col quarter
    const int m0   = blockIdx.y * 64;   // 7 tiles
    const int n0   = blockIdx.x * 96;   // 5 tiles (480 >= 400)
    const int b    = blockIdx.z;
    const int w0   = n0 - m0 + 399;

    const float* A = P + (long)b * SEQ * PW;        // Q
    const float* B = P + (long)b * SEQ * PW + DM;   // K

    const uint32_t uA = (uint32_t)__cvta_generic_to_shared(Asb);
    const uint32_t uB = (uint32_t)__cvta_generic_to_shared(Bsb);
    const uint32_t uS = (uint32_t)__cvta_generic_to_shared(Ss);

    // A loader: 2 quads; rows (tid>>3)+{0,32}, col (tid&7)*4
    const int arow = tid >> 3;
    const int acol = (tid & 7) * 4;
    const bool aok0 = (m0 + arow) < SEQ;
    const bool aok1 = (m0 + arow + 32) < SEQ;
    const float* aptr = A + (long)(m0 + arow) * PW + acol;
    const uint32_t adst = uA + (uint32_t)(arow * 36 + acol) * 4;

    float acc[2][3][4];
#pragma unroll
    for (int mt = 0; mt < 2; mt++)
#pragma unroll
        for (int nt = 0; nt < 3; nt++)
#pragma unroll
            for (int r = 0; r < 4; r++) acc[mt][nt][r] = 0.f;

    // S prefetch: 64 rows x 25 quads = 1600 quads, 8 chunks of 200
    auto s_chunk = [&](int ci) {
        if (tid < 200) {
            const int gq = ci * 200 + tid;       // < 1600
            const int r = gq / 25;
            const int q = gq % 25;
            const int base = (w0 - r) & ~3;
            const int col = base + q * 4;
            const bool ok = ((m0 + r) < SEQ) && (col >= 0) && (col < 893);
            const float* src = S + (long)(b * SEQ + m0 + r) * ND2 + col;
            cpa16(uS + (uint32_t)(r * SROW + q * 4) * 4, src, ok);
        }
    };

    auto load_stage = [&](int buf, int k0, int ci) {
        const uint32_t ao = (uint32_t)buf * (ASZ * 4);
        const uint32_t bo = (uint32_t)buf * (BSZ * 4);
        cpa16(adst + ao, aptr + k0, aok0);
        cpa16(adst + ao + (uint32_t)(32 * 36) * 4, aptr + (long)32 * PW + k0, aok1);
        // B (NT): 96 rows x 32 k = 768 quads, 3 per thread
#pragma unroll
        for (int j = 0; j < 3; j++) {
            const int q = tid + j * 256;
            const int r = q >> 3;                // 0..95
            const int c = (q & 7) * 4;
            const bool ok = (n0 + r) < SEQ;
            cpa16(uB + bo + (uint32_t)(r * 36 + c) * 4,
                  B + (long)(n0 + r) * PW + k0 + c, ok);
        }
        s_chunk(ci);
        cpa_commit();
    };

    const int nk = DM >> 5;   // 8
    load_stage(0, 0, 0);
    cpa_wait0();
    __syncthreads();

    int buf = 0;
    for (int kt = 0; kt < nk; kt++) {
        const bool more = (kt + 1 < nk);
        if (more) load_stage(buf ^ 1, (kt + 1) << 5, kt + 1);

        const float* Astage = Asb + buf * ASZ;
        const float* Bstage = Bsb + buf * BSZ;
#pragma unroll
        for (int h = 0; h < 4; h++) {
            const int c = h * 8 + (lane & 3);
            uint32_t af[2][4];
            uint32_t bf[3][2];
            const float* abase = Astage + (wm * 32 + (lane >> 2)) * 36 + c;
#pragma unroll
            for (int mt = 0; mt < 2; mt++) {
                af[mt][0] = __float_as_uint(abase[(mt * 16    ) * 36    ]);
                af[mt][1] = __float_as_uint(abase[(mt * 16 + 8) * 36    ]);
                af[mt][2] = __float_as_uint(abase[(mt * 16    ) * 36 + 4]);
                af[mt][3] = __float_as_uint(abase[(mt * 16 + 8) * 36 + 4]);
            }
#pragma unroll
            for (int nt = 0; nt < 3; nt++) {
                const int nB = wn * 24 + nt * 8 + (lane >> 2);
                bf[nt][0] = __float_as_uint(Bstage[nB * 36 + c]);
                bf[nt][1] = __float_as_uint(Bstage[nB * 36 + c + 4]);
            }
#pragma unroll
            for (int mt = 0; mt < 2; mt++)
#pragma unroll
                for (int nt = 0; nt < 3; nt++)
                    mma8(acc[mt][nt], af[mt], bf[nt]);
        }

        if (more) {
            cpa_wait0();
            __syncthreads();
            buf ^= 1;
        }
    }

    // ---- fused combine epilogue (S from smem) ----
#pragma unroll
    for (int mt = 0; mt < 2; mt++) {
        const int ibase = m0 + wm * 32 + mt * 16 + (lane >> 2);
#pragma unroll
        for (int half = 0; half < 2; half++) {
            const int i = ibase + half * 8;
            if (i >= SEQ) continue;
            const int r = i - m0;
            const float* srow = Ss + r * SROW + ((w0 - r) & 3) - n0;
            const long obase = (long)b * SEQ * SEQ + (long)i * SEQ;
#pragma unroll
            for (int nt = 0; nt < 3; nt++) {
                const int cc = n0 + wn * 24 + nt * 8 + (lane & 3) * 2;
                if (cc >= SEQ) continue;   // cc even, so cc+1 <= 399
                const float v0 = (acc[mt][nt][half * 2 + 0] + srow[cc])     * 0.0625f;
                const float v1 = (acc[mt][nt][half * 2 + 1] + srow[cc + 1]) * 0.0625f;
                *(float2*)&out[obase + cc] = make_float2(v0, v1);
            }
        }
    }
}

extern "C" void kernel_launch(void* const* d_in, const int* in_sizes, int n_in,
                              void* d_out, int out_size)
{
    const float* x    = (const float*)d_in[0];  // (8,400,512)
    const int*   mask = (const int*)  d_in[1];  // (8,400)
    const float* w_q  = (const float*)d_in[2];  // (512,256)
    const float* w_q2 = (const float*)d_in[3];  // (512,256)
    const float* w_k  = (const float*)d_in[4];  // (512,256)
    const float* w_k2 = (const float*)d_in[5];  // (256,256)
    const float* rel  = (const float*)d_in[6];  // (1,400,400,256)
    float* out = (float*)d_out;

    float *Wcat, *P, *RT, *S;
    cudaGetSymbolAddress((void**)&Wcat, g_Wcat);
    cudaGetSymbolAddress((void**)&P,    g_P);
    cudaGetSymbolAddress((void**)&RT,   g_RT);
    cudaGetSymbolAddress((void**)&S,    g_S);

    const int smemP = (2 * 64 * 36 + 2 * 32 * 136) * 4;             // 53248
    const int smemS = (2 * 64 * 36 + 2 * 32 * 104) * 4;             // 45056
    const int smemE = (2 * 64 * 36 + 2 * 96 * 36 + 64 * 104) * 4;   // 72704
    cudaFuncSetAttribute(mmaT<true, false, true, 128>,
        cudaFuncAttributeMaxDynamicSharedMemorySize, smemP);
    cudaFuncSetAttribute(mmaT<false, true, false, 96>,
        cudaFuncAttributeMaxDynamicSharedMemorySize, smemS);
    cudaFuncSetAttribute(mmaE,
        cudaFuncAttributeMaxDynamicSharedMemorySize, smemE);

    // 1) Setup (Wcat, RT, mask half of out) — one launch
    setup_all<<<SB4, 256>>>(w_q, w_k, w_q2, w_k2, rel, mask,
                            Wcat, RT, out, out_size);

    // 2) P = x @ Wcat (3200x768x512); A-fragments cvt'd to tf32 in-register
    mmaT<true, false, true, 128><<<dim3(PW / 128, BS / 64), 256, smemP>>>(
        x, Wcat, P, SD, SD, PW, PW);

    // 3) S band = P[:,512:768) @ RT, consumed diagonal band only.
    //    Per (b, i0): needed m in [max(0,336-i0), 798-i0] (width <= 463);
    //    5 tiles of 96 from nbase = max(0,336-i0) cover it. 280 CTAs.
    mmaT<false, true, false, 96><<<dim3(5, 7, BATCH), 256, smemS>>>(
        P + SD, RT, S, DM, PW, ND2, ND2);

    // 4) E = Q @ K^T fused with combine + smem S window (280 CTAs)
    mmaE<<<dim3(5, 7, BATCH), 256, smemE>>>(P, S, out);
}